// round 9
// baseline (speedup 1.0000x reference)
#include <cuda_runtime.h>
#include <cuda_bf16.h>
#include <cuda_fp16.h>
#include <math.h>
#include <stdint.h>

// Problem constants (fixed by the benchmark shapes)
#define BB   4
#define NN   16384
#define CC   256
#define C3   768
#define TT   64
#define HH   8
#define DD   32
#define GS   128
#define NG   128
#define NCH  128
#define CHSZ 128

// -------- scratch (device globals) --------
__device__ int   g_tkid[BB * NN];
__device__ int   g_sortidx[BB * NN];
__device__ int   g_hist[BB * TT * NCH];
__device__ __nv_bfloat16 g_y_hi[(size_t)BB * NN * CC];
__device__ __nv_bfloat16 g_y_lo[(size_t)BB * NN * CC];
__device__ __nv_bfloat16 g_w_hi[CC * CC];
__device__ __nv_bfloat16 g_w_lo[CC * CC];

// ---------------- PTX helpers ----------------
__device__ __forceinline__ uint32_t smem_u32(const void* p) {
    return (uint32_t)__cvta_generic_to_shared(p);
}
__device__ __forceinline__ void ldm_x4(uint32_t* r, uint32_t a) {
    asm volatile("ldmatrix.sync.aligned.m8n8.x4.shared.b16 {%0,%1,%2,%3},[%4];"
                 : "=r"(r[0]), "=r"(r[1]), "=r"(r[2]), "=r"(r[3]) : "r"(a));
}
__device__ __forceinline__ void ldm_x4_t(uint32_t* r, uint32_t a) {
    asm volatile("ldmatrix.sync.aligned.m8n8.x4.trans.shared.b16 {%0,%1,%2,%3},[%4];"
                 : "=r"(r[0]), "=r"(r[1]), "=r"(r[2]), "=r"(r[3]) : "r"(a));
}
__device__ __forceinline__ void mma_bf16(float* c, const uint32_t* a, uint32_t b0, uint32_t b1) {
    asm volatile(
        "mma.sync.aligned.m16n8k16.row.col.f32.bf16.bf16.f32 "
        "{%0,%1,%2,%3},{%4,%5,%6,%7},{%8,%9},{%0,%1,%2,%3};"
        : "+f"(c[0]), "+f"(c[1]), "+f"(c[2]), "+f"(c[3])
        : "r"(a[0]), "r"(a[1]), "r"(a[2]), "r"(a[3]), "r"(b0), "r"(b1));
}
__device__ __forceinline__ void mma_f16(float* c, const uint32_t* a, uint32_t b0, uint32_t b1) {
    asm volatile(
        "mma.sync.aligned.m16n8k16.row.col.f32.f16.f16.f32 "
        "{%0,%1,%2,%3},{%4,%5,%6,%7},{%8,%9},{%0,%1,%2,%3};"
        : "+f"(c[0]), "+f"(c[1]), "+f"(c[2]), "+f"(c[3])
        : "r"(a[0]), "r"(a[1]), "r"(a[2]), "r"(a[3]), "r"(b0), "r"(b1));
}
__device__ __forceinline__ uint32_t packh2(float x, float y) {
    __half2 t = __floats2half2_rn(x, y);
    return *(uint32_t*)&t;
}
__device__ __forceinline__ void cp16(void* smem_dst, const void* gsrc) {
    asm volatile("cp.async.cg.shared.global [%0], [%1], 16;"
                 :: "r"(smem_u32(smem_dst)), "l"(gsrc));
}
#define CP_COMMIT()  asm volatile("cp.async.commit_group;")
#define CP_WAIT(N)   asm volatile("cp.async.wait_group %0;" :: "n"(N))

extern __shared__ __align__(16) char dynsm[];

// ---------------- 1+2a) fused argmax + histogram + W split ----------------
__global__ void k_argmax_hist(const float* __restrict__ sim, const float* __restrict__ W) {
    __shared__ int h[TT];
    int b  = blockIdx.x / NCH;
    int ch = blockIdx.x % NCH;
    int t  = threadIdx.x;
    {
        int wi = blockIdx.x * CHSZ + t;
        float v = W[wi];
        __nv_bfloat16 hi = __float2bfloat16(v);
        g_w_hi[wi] = hi;
        g_w_lo[wi] = __float2bfloat16(v - __bfloat162float(hi));
    }
    if (t < TT) h[t] = 0;
    int idx = b * NN + ch * CHSZ + t;
    const float4* p = (const float4*)(sim + (size_t)idx * TT);
    float best = -3.402823466e38f;
    int bi = 0;
#pragma unroll
    for (int i = 0; i < 16; i++) {
        float4 v = p[i];
        if (v.x > best) { best = v.x; bi = 4 * i + 0; }
        if (v.y > best) { best = v.y; bi = 4 * i + 1; }
        if (v.z > best) { best = v.z; bi = 4 * i + 2; }
        if (v.w > best) { best = v.w; bi = 4 * i + 3; }
    }
    g_tkid[idx] = bi;
    __syncthreads();
    atomicAdd(&h[bi], 1);
    __syncthreads();
    if (t < TT)
        g_hist[(b * TT + t) * NCH + ch] = h[t];
}

// ---------------- 2b) exclusive scan ----------------
__global__ void k_scan() {
    __shared__ int tot[256];
    int b = blockIdx.x;
    int* base = g_hist + b * TT * NCH;
    int t = threadIdx.x;
    int v[32];
    int s = 0;
#pragma unroll
    for (int i = 0; i < 32; i++) { v[i] = base[t * 32 + i]; s += v[i]; }
    tot[t] = s;
    __syncthreads();
    if (t == 0) {
        int acc = 0;
        for (int i = 0; i < 256; i++) { int x = tot[i]; tot[i] = acc; acc += x; }
    }
    __syncthreads();
    int ex = tot[t];
#pragma unroll
    for (int i = 0; i < 32; i++) { int x = v[i]; base[t * 32 + i] = ex; ex += x; }
}

// ---------------- 2c) parallel stable scatter ----------------
__global__ void k_scatter_par() {
    __shared__ int whist[4][TT];
    int b  = blockIdx.x / NCH;
    int ch = blockIdx.x % NCH;
    int t  = threadIdx.x;
    int lane = t & 31, w = t >> 5;
    ((int*)whist)[t] = 0;
    ((int*)whist)[t + 128] = 0;
    int key = g_tkid[b * NN + ch * CHSZ + t];
    __syncthreads();
    unsigned mask = __match_any_sync(0xffffffffu, key);
    int wrank = __popc(mask & ((1u << lane) - 1u));
    if (lane == (__ffs(mask) - 1))
        whist[w][key] = __popc(mask);
    __syncthreads();
    int off = 0;
#pragma unroll
    for (int w2 = 0; w2 < 3; w2++)
        if (w2 < w) off += whist[w2][key];
    int pos = g_hist[(b * TT + key) * NCH + ch] + off + wrank;
    g_sortidx[b * NN + pos] = ch * CHSZ + t;
}

// ---------------- 3) tensor-core attention, flash-chunked, coalesced gather ----------------
// Block = one (b, g, h), 256 threads = 8 warps, warp owns 16 query rows (all cols).
// QK: bf16x3. PV: fp16. Gather is tensor-major chunked: warp reads 4 contiguous
// 128B token-slices per LDG (vs 16 scattered lines before).
#define AST 40
#define SM_Q_HI 0
#define SM_Q_LO (128 * AST)
#define SM_K_HI (2 * 128 * AST)
#define SM_K_LO (3 * 128 * AST)
#define SM_VF   (4 * 128 * AST)
#define SM_TOK  (5 * 128 * AST)
#define SMEM_ATT_BYTES (5 * 128 * AST * 2 + 128 * 4)

__global__ void __launch_bounds__(256, 3)
k_attn_mma(const float* __restrict__ qkv, const float* __restrict__ logit_scale) {
    __nv_bfloat16* sm = (__nv_bfloat16*)dynsm;
    __nv_bfloat16* Qh = sm + SM_Q_HI;
    __nv_bfloat16* Ql = sm + SM_Q_LO;
    __nv_bfloat16* Kh = sm + SM_K_HI;
    __nv_bfloat16* Kl = sm + SM_K_LO;
    __half*        Vf = (__half*)(sm + SM_VF);
    int* toks = (int*)(sm + SM_TOK);

    int g = blockIdx.x, h = blockIdx.y, b = blockIdx.z;
    int tid = threadIdx.x, lane = tid & 31, warp = tid >> 5;

    // ---- stage sorted token ids ----
    if (tid < GS) toks[tid] = g_sortidx[b * NN + g * GS + tid];
    __syncthreads();

    // ---- coalesced gather: 3072 16B chunks, tensor-major ----
    // chunk c: tensor = c>>10 (0=Q,1=K,2=V), row = (c>>3)&127, sub = c&7.
    // A warp's 32 consecutive chunks = 4 token rows x 128B contiguous.
    {
        const float* qb = qkv + (size_t)b * NN * C3 + h * DD;
#pragma unroll
        for (int i = 0; i < 12; i++) {
            int c = i * 256 + tid;
            int tsel = i >> 2;                      // compile-time per iteration
            int row = (c >> 3) & 127;
            int sub = c & 7;
            float4 x = *(const float4*)(qb + (size_t)toks[row] * C3 + tsel * CC + sub * 4);
            if (tsel < 2) {
                __nv_bfloat162 h01 = __floats2bfloat162_rn(x.x, x.y);
                __nv_bfloat162 h23 = __floats2bfloat162_rn(x.z, x.w);
                float2 f01 = __bfloat1622float2(h01);
                float2 f23 = __bfloat1622float2(h23);
                __nv_bfloat162 l01 = __floats2bfloat162_rn(x.x - f01.x, x.y - f01.y);
                __nv_bfloat162 l23 = __floats2bfloat162_rn(x.z - f23.x, x.w - f23.y);
                __nv_bfloat16* dh = (tsel == 0 ? Qh : Kh) + row * AST + sub * 4;
                __nv_bfloat16* dl = (tsel == 0 ? Ql : Kl) + row * AST + sub * 4;
                *(uint2*)dh = make_uint2(*(uint32_t*)&h01, *(uint32_t*)&h23);
                *(uint2*)dl = make_uint2(*(uint32_t*)&l01, *(uint32_t*)&l23);
            } else {
                __half2 p01 = __floats2half2_rn(x.x, x.y);
                __half2 p23 = __floats2half2_rn(x.z, x.w);
                *(uint2*)(Vf + row * AST + sub * 4) =
                    make_uint2(*(uint32_t*)&p01, *(uint32_t*)&p23);
            }
        }
    }
    // fold softmax scale and log2(e) into the logits once: p = exp2(s*sc2 - M2)
    float sc2 = __expf(fminf(logit_scale[0], 4.605170185988091f)) * 1.44269504088896f;
    __syncthreads();

    int m0 = warp * 16;
    int l16 = lane & 15;

    // Q hi fragments resident; lo reloaded per chunk
    uint32_t qh[2][4];
#pragma unroll
    for (int ks = 0; ks < 2; ks++)
        ldm_x4(qh[ks], smem_u32(Qh + (m0 + l16) * AST + ks * 16 + (lane >> 4) * 8));

    float o[4][4];
#pragma unroll
    for (int nf = 0; nf < 4; nf++)
#pragma unroll
        for (int r = 0; r < 4; r++) o[nf][r] = 0.0f;
    float m01 = -1e30f, m23 = -1e30f, l01 = 0.0f, l23 = 0.0f;

#pragma unroll
    for (int chnk = 0; chnk < 2; chnk++) {
        int c0 = chnk * 64;
        uint32_t ql[2][4];
#pragma unroll
        for (int ks = 0; ks < 2; ks++)
            ldm_x4(ql[ks], smem_u32(Ql + (m0 + l16) * AST + ks * 16 + (lane >> 4) * 8));

        float s[8][4];
#pragma unroll
        for (int nf = 0; nf < 8; nf++)
#pragma unroll
            for (int r = 0; r < 4; r++) s[nf][r] = 0.0f;

#pragma unroll
        for (int p2 = 0; p2 < 4; p2++) {
            int j0 = c0 + p2 * 16;
#pragma unroll
            for (int ks = 0; ks < 2; ks++) {
                uint32_t kb[4], kl4[4];
                int krow = j0 + ((lane >> 4) << 3) + (lane & 7);
                int kcol = ks * 16 + ((lane >> 3) & 1) * 8;
                ldm_x4(kb,  smem_u32(Kh + krow * AST + kcol));
                ldm_x4(kl4, smem_u32(Kl + krow * AST + kcol));
                mma_bf16(s[2 * p2],     qh[ks], kb[0],  kb[1]);
                mma_bf16(s[2 * p2],     qh[ks], kl4[0], kl4[1]);
                mma_bf16(s[2 * p2],     ql[ks], kb[0],  kb[1]);
                mma_bf16(s[2 * p2 + 1], qh[ks], kb[2],  kb[3]);
                mma_bf16(s[2 * p2 + 1], qh[ks], kl4[2], kl4[3]);
                mma_bf16(s[2 * p2 + 1], ql[ks], kb[2],  kb[3]);
            }
        }

        // scale fold + chunk row-max (quad shfl)
        float cm01 = -1e30f, cm23 = -1e30f;
#pragma unroll
        for (int nf = 0; nf < 8; nf++) {
#pragma unroll
            for (int r = 0; r < 4; r++) s[nf][r] *= sc2;
            cm01 = fmaxf(cm01, fmaxf(s[nf][0], s[nf][1]));
            cm23 = fmaxf(cm23, fmaxf(s[nf][2], s[nf][3]));
        }
        cm01 = fmaxf(cm01, __shfl_xor_sync(0xffffffffu, cm01, 1));
        cm01 = fmaxf(cm01, __shfl_xor_sync(0xffffffffu, cm01, 2));
        cm23 = fmaxf(cm23, __shfl_xor_sync(0xffffffffu, cm23, 1));
        cm23 = fmaxf(cm23, __shfl_xor_sync(0xffffffffu, cm23, 2));

        // online update: rescale running O and l
        float nm01 = fmaxf(m01, cm01), nm23 = fmaxf(m23, cm23);
        float cor01 = exp2f(m01 - nm01), cor23 = exp2f(m23 - nm23);
        m01 = nm01; m23 = nm23;
#pragma unroll
        for (int nf = 0; nf < 4; nf++) {
            o[nf][0] *= cor01; o[nf][1] *= cor01;
            o[nf][2] *= cor23; o[nf][3] *= cor23;
        }

        float sum01 = 0.0f, sum23 = 0.0f;
#pragma unroll
        for (int nf = 0; nf < 8; nf++) {
            float e0 = exp2f(s[nf][0] - m01);
            float e1 = exp2f(s[nf][1] - m01);
            float e2 = exp2f(s[nf][2] - m23);
            float e3 = exp2f(s[nf][3] - m23);
            s[nf][0] = e0; s[nf][1] = e1; s[nf][2] = e2; s[nf][3] = e3;
            sum01 += e0 + e1;
            sum23 += e2 + e3;
        }
        sum01 += __shfl_xor_sync(0xffffffffu, sum01, 1);
        sum01 += __shfl_xor_sync(0xffffffffu, sum01, 2);
        sum23 += __shfl_xor_sync(0xffffffffu, sum23, 1);
        sum23 += __shfl_xor_sync(0xffffffffu, sum23, 2);
        l01 = l01 * cor01 + sum01;
        l23 = l23 * cor23 + sum23;

        // PV over this chunk's 64 k-rows
#pragma unroll
        for (int kj = 0; kj < 4; kj++) {
            int f0 = 2 * kj, f1 = 2 * kj + 1;
            uint32_t ph[4];
            ph[0] = packh2(s[f0][0], s[f0][1]);
            ph[1] = packh2(s[f0][2], s[f0][3]);
            ph[2] = packh2(s[f1][0], s[f1][1]);
            ph[3] = packh2(s[f1][2], s[f1][3]);
            int vrow = c0 + kj * 16 + l16;
#pragma unroll
            for (int dh2 = 0; dh2 < 2; dh2++) {
                uint32_t vf[4];
                ldm_x4_t(vf, smem_u32(Vf + vrow * AST + dh2 * 16 + ((lane >> 4) << 3)));
                mma_f16(o[2 * dh2],     ph, vf[0], vf[1]);
                mma_f16(o[2 * dh2 + 1], ph, vf[2], vf[3]);
            }
        }
    }

    // ---- epilogue: normalize, split hi/lo, scatter to original token rows ----
    float inv0 = 1.0f / l01, inv1 = 1.0f / l23;
    int r0 = m0 + (lane >> 2);
    int tok0 = toks[r0], tok1 = toks[r0 + 8];
    size_t ob0 = (size_t)(b * NN + tok0) * CC + h * DD + (lane & 3) * 2;
    size_t ob1 = (size_t)(b * NN + tok1) * CC + h * DD + (lane & 3) * 2;
#pragma unroll
    for (int nf = 0; nf < 4; nf++) {
        float v0 = o[nf][0] * inv0, v1 = o[nf][1] * inv0;
        float v2 = o[nf][2] * inv1, v3 = o[nf][3] * inv1;
        __nv_bfloat162 a01 = __floats2bfloat162_rn(v0, v1);
        __nv_bfloat162 a23 = __floats2bfloat162_rn(v2, v3);
        float2 fa = __bfloat1622float2(a01), fb = __bfloat1622float2(a23);
        __nv_bfloat162 b01 = __floats2bfloat162_rn(v0 - fa.x, v1 - fa.y);
        __nv_bfloat162 b23 = __floats2bfloat162_rn(v2 - fb.x, v3 - fb.y);
        *(__nv_bfloat162*)(g_y_hi + ob0 + nf * 8) = a01;
        *(__nv_bfloat162*)(g_y_lo + ob0 + nf * 8) = b01;
        *(__nv_bfloat162*)(g_y_hi + ob1 + nf * 8) = a23;
        *(__nv_bfloat162*)(g_y_lo + ob1 + nf * 8) = b23;
    }
}

// ---------------- 4) projection: bf16x3 MMA, cp.async double-buffered ----------------
#define PST  40
#define PPL  (128 * PST)
#define PSTG (4 * PPL)
#define SMEM_PROJ_BYTES (2 * PSTG * 2)

__global__ void __launch_bounds__(256)
k_proj2(const float* __restrict__ bias, float* __restrict__ out) {
    __nv_bfloat16* sm = (__nv_bfloat16*)dynsm;

    int tid  = threadIdx.x;
    int lane = tid & 31;
    int warp = tid >> 5;
    int row0 = blockIdx.x * 128;
    int col0 = blockIdx.y * 128;
    int m_off = (warp & 3) * 32;
    int n_off = (warp >> 2) * 64;
    int l16 = lane & 15;

    int c0 = tid * 2;
    int rA0 = c0 >> 2, qA0 = (c0 & 3) * 8;
    int rA1 = (c0 + 1) >> 2, qA1 = ((c0 + 1) & 3) * 8;

    const __nv_bfloat16* gA_hi = g_y_hi + (size_t)row0 * CC;
    const __nv_bfloat16* gA_lo = g_y_lo + (size_t)row0 * CC;
    const __nv_bfloat16* gB_hi = g_w_hi + (size_t)col0 * CC;
    const __nv_bfloat16* gB_lo = g_w_lo + (size_t)col0 * CC;

    auto load_stage = [&](int st, int k0) {
        __nv_bfloat16* Ah = sm + st * PSTG;
        __nv_bfloat16* Al = Ah + PPL;
        __nv_bfloat16* Bh = Al + PPL;
        __nv_bfloat16* Bl = Bh + PPL;
        cp16(Ah + rA0 * PST + qA0, gA_hi + (size_t)rA0 * CC + k0 + qA0);
        cp16(Ah + rA1 * PST + qA1, gA_hi + (size_t)rA1 * CC + k0 + qA1);
        cp16(Al + rA0 * PST + qA0, gA_lo + (size_t)rA0 * CC + k0 + qA0);
        cp16(Al + rA1 * PST + qA1, gA_lo + (size_t)rA1 * CC + k0 + qA1);
        cp16(Bh + rA0 * PST + qA0, gB_hi + (size_t)rA0 * CC + k0 + qA0);
        cp16(Bh + rA1 * PST + qA1, gB_hi + (size_t)rA1 * CC + k0 + qA1);
        cp16(Bl + rA0 * PST + qA0, gB_lo + (size_t)rA0 * CC + k0 + qA0);
        cp16(Bl + rA1 * PST + qA1, gB_lo + (size_t)rA1 * CC + k0 + qA1);
        CP_COMMIT();
    };

    float c[2][8][4];
#pragma unroll
    for (int mf = 0; mf < 2; mf++)
#pragma unroll
        for (int nf = 0; nf < 8; nf++)
#pragma unroll
            for (int r = 0; r < 4; r++) c[mf][nf][r] = 0.0f;

    load_stage(0, 0);

    for (int kt = 0; kt < 8; kt++) {
        if (kt + 1 < 8) {
            load_stage((kt + 1) & 1, (kt + 1) * 32);
            CP_WAIT(1);
        } else {
            CP_WAIT(0);
        }
        __syncthreads();

        __nv_bfloat16* Ah = sm + (kt & 1) * PSTG;
        __nv_bfloat16* Al = Ah + PPL;
        __nv_bfloat16* Bh = Al + PPL;
        __nv_bfloat16* Bl = Bh + PPL;

#pragma unroll
        for (int kk = 0; kk < 32; kk += 16) {
            uint32_t bh[8][2], bl[8][2];
#pragma unroll
            for (int np = 0; np < 4; np++) {
                uint32_t t4[4];
                int brow = n_off + np * 16 + ((lane >> 4) << 3) + (lane & 7);
                int bcol = kk + ((lane >> 3) & 1) * 8;
                ldm_x4(t4, smem_u32(Bh + brow * PST + bcol));
                bh[2 * np][0] = t4[0]; bh[2 * np][1] = t4[1];
                bh[2 * np + 1][0] = t4[2]; bh[2 * np + 1][1] = t4[3];
                ldm_x4(t4, smem_u32(Bl + brow * PST + bcol));
                bl[2 * np][0] = t4[0]; bl[2 * np][1] = t4[1];
                bl[2 * np + 1][0] = t4[2]; bl[2 * np + 1][1] = t4[3];
            }
#pragma unroll
            for (int mf = 0; mf < 2; mf++) {
                uint32_t ah[4], al[4];
                int arow = m_off + mf * 16 + l16;
                ldm_x4(ah, smem_u32(Ah + arow * PST + kk + (lane >> 4) * 8));
                ldm_x4(al, smem_u32(Al + arow * PST + kk + (lane >> 4) * 8));
#pragma unroll
                for (int nf = 0; nf < 8; nf++) {
                    mma_bf16(c[mf][nf], ah, bh[nf][0], bh[nf][1]);
                    mma_bf16(c[mf][nf], ah, bl[nf][0], bl[nf][1]);
                    mma_bf16(c[mf][nf], al, bh[nf][0], bh[nf][1]);
                }
            }
        }
        __syncthreads();
    }

#pragma unroll
    for (int mf = 0; mf < 2; mf++) {
#pragma unroll
        for (int nf = 0; nf < 8; nf++) {
            int rg = row0 + m_off + mf * 16 + (lane >> 2);
            int cg = col0 + n_off + nf * 8 + (lane & 3) * 2;
            float b0 = bias[cg], b1 = bias[cg + 1];
            float2* o0 = (float2*)(out + (size_t)rg * CC + cg);
            float2* o1 = (float2*)(out + (size_t)(rg + 8) * CC + cg);
            *o0 = make_float2(c[mf][nf][0] + b0, c[mf][nf][1] + b1);
            *o1 = make_float2(c[mf][nf][2] + b0, c[mf][nf][3] + b1);
        }
    }
}

// ---------------- launch ----------------
extern "C" void kernel_launch(void* const* d_in, const int* in_sizes, int n_in,
                              void* d_out, int out_size) {
    const float* qkv         = (const float*)d_in[0];
    const float* sim         = (const float*)d_in[1];
    const float* proj_w      = (const float*)d_in[2];
    const float* proj_b      = (const float*)d_in[3];
    const float* logit_scale = (const float*)d_in[4];
    float* out = (float*)d_out;

    k_argmax_hist<<<BB * NCH, CHSZ>>>(sim, proj_w);
    k_scan<<<BB, 256>>>();
    k_scatter_par<<<BB * NCH, CHSZ>>>();

    cudaFuncSetAttribute(k_attn_mma, cudaFuncAttributeMaxDynamicSharedMemorySize, SMEM_ATT_BYTES);
    k_attn_mma<<<dim3(NG, HH, BB), 256, SMEM_ATT_BYTES>>>(qkv, logit_scale);

    cudaFuncSetAttribute(k_proj2, cudaFuncAttributeMaxDynamicSharedMemorySize, SMEM_PROJ_BYTES);
    k_proj2<<<dim3((BB * NN) / 128, CC / 128), 256, SMEM_PROJ_BYTES>>>(proj_b, out);
}

// round 10
// speedup vs baseline: 1.2892x; 1.2892x over previous
#include <cuda_runtime.h>
#include <cuda_bf16.h>
#include <cuda_fp16.h>
#include <math.h>
#include <stdint.h>

// Problem constants (fixed by the benchmark shapes)
#define BB   4
#define NN   16384
#define CC   256
#define C3   768
#define TT   64
#define HH   8
#define DD   32
#define GS   128
#define NG   128
#define NCH  128
#define CHSZ 128

// -------- scratch (device globals) --------
__device__ int   g_tkid[BB * NN];
__device__ int   g_sortidx[BB * NN];
__device__ int   g_hist[BB * TT * NCH];
__device__ __half g_y[(size_t)BB * NN * CC];     // attention out, single fp16 plane
__device__ __half g_w_hi[CC * CC];               // W split fp16 planes
__device__ __half g_w_lo[CC * CC];

// ---------------- PTX helpers ----------------
__device__ __forceinline__ uint32_t smem_u32(const void* p) {
    return (uint32_t)__cvta_generic_to_shared(p);
}
__device__ __forceinline__ void ldm_x4(uint32_t* r, uint32_t a) {
    asm volatile("ldmatrix.sync.aligned.m8n8.x4.shared.b16 {%0,%1,%2,%3},[%4];"
                 : "=r"(r[0]), "=r"(r[1]), "=r"(r[2]), "=r"(r[3]) : "r"(a));
}
__device__ __forceinline__ void ldm_x4_t(uint32_t* r, uint32_t a) {
    asm volatile("ldmatrix.sync.aligned.m8n8.x4.trans.shared.b16 {%0,%1,%2,%3},[%4];"
                 : "=r"(r[0]), "=r"(r[1]), "=r"(r[2]), "=r"(r[3]) : "r"(a));
}
__device__ __forceinline__ void mma_bf16(float* c, const uint32_t* a, uint32_t b0, uint32_t b1) {
    asm volatile(
        "mma.sync.aligned.m16n8k16.row.col.f32.bf16.bf16.f32 "
        "{%0,%1,%2,%3},{%4,%5,%6,%7},{%8,%9},{%0,%1,%2,%3};"
        : "+f"(c[0]), "+f"(c[1]), "+f"(c[2]), "+f"(c[3])
        : "r"(a[0]), "r"(a[1]), "r"(a[2]), "r"(a[3]), "r"(b0), "r"(b1));
}
__device__ __forceinline__ void mma_f16(float* c, const uint32_t* a, uint32_t b0, uint32_t b1) {
    asm volatile(
        "mma.sync.aligned.m16n8k16.row.col.f32.f16.f16.f32 "
        "{%0,%1,%2,%3},{%4,%5,%6,%7},{%8,%9},{%0,%1,%2,%3};"
        : "+f"(c[0]), "+f"(c[1]), "+f"(c[2]), "+f"(c[3])
        : "r"(a[0]), "r"(a[1]), "r"(a[2]), "r"(a[3]), "r"(b0), "r"(b1));
}
__device__ __forceinline__ uint32_t packh2(float x, float y) {
    __half2 t = __floats2half2_rn(x, y);
    return *(uint32_t*)&t;
}
__device__ __forceinline__ void cp16(void* smem_dst, const void* gsrc) {
    asm volatile("cp.async.cg.shared.global [%0], [%1], 16;"
                 :: "r"(smem_u32(smem_dst)), "l"(gsrc));
}
#define CP_COMMIT()  asm volatile("cp.async.commit_group;")
#define CP_WAIT(N)   asm volatile("cp.async.wait_group %0;" :: "n"(N))

extern __shared__ __align__(16) char dynsm[];

// ---------------- 1+2a) fused argmax + histogram + W split (fp16) ----------------
__global__ void k_argmax_hist(const float* __restrict__ sim, const float* __restrict__ W) {
    __shared__ int h[TT];
    int b  = blockIdx.x / NCH;
    int ch = blockIdx.x % NCH;
    int t  = threadIdx.x;
    {
        int wi = blockIdx.x * CHSZ + t;
        float v = W[wi];
        __half hi = __float2half_rn(v);
        g_w_hi[wi] = hi;
        g_w_lo[wi] = __float2half_rn(v - __half2float(hi));
    }
    if (t < TT) h[t] = 0;
    int idx = b * NN + ch * CHSZ + t;
    const float4* p = (const float4*)(sim + (size_t)idx * TT);
    float best = -3.402823466e38f;
    int bi = 0;
#pragma unroll
    for (int i = 0; i < 16; i++) {
        float4 v = p[i];
        if (v.x > best) { best = v.x; bi = 4 * i + 0; }
        if (v.y > best) { best = v.y; bi = 4 * i + 1; }
        if (v.z > best) { best = v.z; bi = 4 * i + 2; }
        if (v.w > best) { best = v.w; bi = 4 * i + 3; }
    }
    g_tkid[idx] = bi;
    __syncthreads();
    atomicAdd(&h[bi], 1);
    __syncthreads();
    if (t < TT)
        g_hist[(b * TT + t) * NCH + ch] = h[t];
}

// ---------------- 2b) exclusive scan ----------------
__global__ void k_scan() {
    __shared__ int tot[256];
    int b = blockIdx.x;
    int* base = g_hist + b * TT * NCH;
    int t = threadIdx.x;
    int v[32];
    int s = 0;
#pragma unroll
    for (int i = 0; i < 32; i++) { v[i] = base[t * 32 + i]; s += v[i]; }
    tot[t] = s;
    __syncthreads();
    if (t == 0) {
        int acc = 0;
        for (int i = 0; i < 256; i++) { int x = tot[i]; tot[i] = acc; acc += x; }
    }
    __syncthreads();
    int ex = tot[t];
#pragma unroll
    for (int i = 0; i < 32; i++) { int x = v[i]; base[t * 32 + i] = ex; ex += x; }
}

// ---------------- 2c) parallel stable scatter ----------------
__global__ void k_scatter_par() {
    __shared__ int whist[4][TT];
    int b  = blockIdx.x / NCH;
    int ch = blockIdx.x % NCH;
    int t  = threadIdx.x;
    int lane = t & 31, w = t >> 5;
    ((int*)whist)[t] = 0;
    ((int*)whist)[t + 128] = 0;
    int key = g_tkid[b * NN + ch * CHSZ + t];
    __syncthreads();
    unsigned mask = __match_any_sync(0xffffffffu, key);
    int wrank = __popc(mask & ((1u << lane) - 1u));
    if (lane == (__ffs(mask) - 1))
        whist[w][key] = __popc(mask);
    __syncthreads();
    int off = 0;
#pragma unroll
    for (int w2 = 0; w2 < 3; w2++)
        if (w2 < w) off += whist[w2][key];
    int pos = g_hist[(b * TT + key) * NCH + ch] + off + wrank;
    g_sortidx[b * NN + pos] = ch * CHSZ + t;
}

// ---------------- 3) tensor-core attention, flash-chunked ----------------
// Grid = (HH, NG, BB): h fastest so the 8 head-blocks of one (b,g) co-run and
// tile each token's contiguous 3KB row across L2 (sequentialized DRAM stream).
// Block = 256 threads = 8 warps, warp owns 16 query rows.
// QK: bf16x3. PV: fp16. Output y: single fp16 plane.
#define AST 40
#define SM_Q_HI 0
#define SM_Q_LO (128 * AST)
#define SM_K_HI (2 * 128 * AST)
#define SM_K_LO (3 * 128 * AST)
#define SM_VF   (4 * 128 * AST)
#define SM_TOK  (5 * 128 * AST)
#define SMEM_ATT_BYTES (5 * 128 * AST * 2 + 128 * 4)

__global__ void __launch_bounds__(256, 3)
k_attn_mma(const float* __restrict__ qkv, const float* __restrict__ logit_scale) {
    __nv_bfloat16* sm = (__nv_bfloat16*)dynsm;
    __nv_bfloat16* Qh = sm + SM_Q_HI;
    __nv_bfloat16* Ql = sm + SM_Q_LO;
    __nv_bfloat16* Kh = sm + SM_K_HI;
    __nv_bfloat16* Kl = sm + SM_K_LO;
    __half*        Vf = (__half*)(sm + SM_VF);
    int* toks = (int*)(sm + SM_TOK);

    int h = blockIdx.x, g = blockIdx.y, b = blockIdx.z;
    int tid = threadIdx.x, lane = tid & 31, warp = tid >> 5;

    // ---- gather: thread t owns token-row t/2, 16-float half (t&1) (high MLP) ----
    {
        int row = tid >> 1, half = tid & 1;
        int tok = g_sortidx[b * NN + g * GS + row];
        if (half == 0) toks[row] = tok;
        size_t base = (size_t)(b * NN + tok) * C3 + h * DD + half * 16;
        int soff = row * AST + half * 16;
#pragma unroll
        for (int tsel = 0; tsel < 2; tsel++) {      // Q, K: bf16 hi/lo split
            const float4* src = (const float4*)(qkv + base + tsel * CC);
            __nv_bfloat16* dh = (tsel == 0 ? Qh : Kh) + soff;
            __nv_bfloat16* dl = (tsel == 0 ? Ql : Kl) + soff;
#pragma unroll
            for (int i = 0; i < 4; i++) {
                float4 x = src[i];
                __nv_bfloat162 h01 = __floats2bfloat162_rn(x.x, x.y);
                __nv_bfloat162 h23 = __floats2bfloat162_rn(x.z, x.w);
                float2 f01 = __bfloat1622float2(h01);
                float2 f23 = __bfloat1622float2(h23);
                __nv_bfloat162 l01 = __floats2bfloat162_rn(x.x - f01.x, x.y - f01.y);
                __nv_bfloat162 l23 = __floats2bfloat162_rn(x.z - f23.x, x.w - f23.y);
                *(uint2*)(dh + i * 4) = make_uint2(*(uint32_t*)&h01, *(uint32_t*)&h23);
                *(uint2*)(dl + i * 4) = make_uint2(*(uint32_t*)&l01, *(uint32_t*)&l23);
            }
        }
        {                                            // V: single fp16 plane
            const float4* src = (const float4*)(qkv + base + 2 * CC);
            __half* dv = Vf + soff;
#pragma unroll
            for (int i = 0; i < 4; i++) {
                float4 x = src[i];
                __half2 p01 = __floats2half2_rn(x.x, x.y);
                __half2 p23 = __floats2half2_rn(x.z, x.w);
                *(uint2*)(dv + i * 4) = make_uint2(*(uint32_t*)&p01, *(uint32_t*)&p23);
            }
        }
    }
    // fold softmax scale and log2(e): p = exp2(s*sc2 - M2)
    float sc2 = __expf(fminf(logit_scale[0], 4.605170185988091f)) * 1.44269504088896f;
    __syncthreads();

    int m0 = warp * 16;
    int l16 = lane & 15;

    uint32_t qh[2][4];
#pragma unroll
    for (int ks = 0; ks < 2; ks++)
        ldm_x4(qh[ks], smem_u32(Qh + (m0 + l16) * AST + ks * 16 + (lane >> 4) * 8));

    float o[4][4];
#pragma unroll
    for (int nf = 0; nf < 4; nf++)
#pragma unroll
        for (int r = 0; r < 4; r++) o[nf][r] = 0.0f;
    float m01 = -1e30f, m23 = -1e30f, l01 = 0.0f, l23 = 0.0f;

#pragma unroll
    for (int chnk = 0; chnk < 2; chnk++) {
        int c0 = chnk * 64;
        uint32_t ql[2][4];
#pragma unroll
        for (int ks = 0; ks < 2; ks++)
            ldm_x4(ql[ks], smem_u32(Ql + (m0 + l16) * AST + ks * 16 + (lane >> 4) * 8));

        float s[8][4];
#pragma unroll
        for (int nf = 0; nf < 8; nf++)
#pragma unroll
            for (int r = 0; r < 4; r++) s[nf][r] = 0.0f;

#pragma unroll
        for (int p2 = 0; p2 < 4; p2++) {
            int j0 = c0 + p2 * 16;
#pragma unroll
            for (int ks = 0; ks < 2; ks++) {
                uint32_t kb[4], kl4[4];
                int krow = j0 + ((lane >> 4) << 3) + (lane & 7);
                int kcol = ks * 16 + ((lane >> 3) & 1) * 8;
                ldm_x4(kb,  smem_u32(Kh + krow * AST + kcol));
                ldm_x4(kl4, smem_u32(Kl + krow * AST + kcol));
                mma_bf16(s[2 * p2],     qh[ks], kb[0],  kb[1]);
                mma_bf16(s[2 * p2],     qh[ks], kl4[0], kl4[1]);
                mma_bf16(s[2 * p2],     ql[ks], kb[0],  kb[1]);
                mma_bf16(s[2 * p2 + 1], qh[ks], kb[2],  kb[3]);
                mma_bf16(s[2 * p2 + 1], qh[ks], kl4[2], kl4[3]);
                mma_bf16(s[2 * p2 + 1], ql[ks], kb[2],  kb[3]);
            }
        }

        // scale fold + chunk row-max (quad shfl)
        float cm01 = -1e30f, cm23 = -1e30f;
#pragma unroll
        for (int nf = 0; nf < 8; nf++) {
#pragma unroll
            for (int r = 0; r < 4; r++) s[nf][r] *= sc2;
            cm01 = fmaxf(cm01, fmaxf(s[nf][0], s[nf][1]));
            cm23 = fmaxf(cm23, fmaxf(s[nf][2], s[nf][3]));
        }
        cm01 = fmaxf(cm01, __shfl_xor_sync(0xffffffffu, cm01, 1));
        cm01 = fmaxf(cm01, __shfl_xor_sync(0xffffffffu, cm01, 2));
        cm23 = fmaxf(cm23, __shfl_xor_sync(0xffffffffu, cm23, 1));
        cm23 = fmaxf(cm23, __shfl_xor_sync(0xffffffffu, cm23, 2));

        // online update
        float nm01 = fmaxf(m01, cm01), nm23 = fmaxf(m23, cm23);
        float cor01 = exp2f(m01 - nm01), cor23 = exp2f(m23 - nm23);
        m01 = nm01; m23 = nm23;
#pragma unroll
        for (int nf = 0; nf < 4; nf++) {
            o[nf][0] *= cor01; o[nf][1] *= cor01;
            o[nf][2] *= cor23; o[nf][3] *= cor23;
        }

        float sum01 = 0.0f, sum23 = 0.0f;
#pragma unroll
        for (int nf = 0; nf < 8; nf++) {
            float e0 = exp2f(s[nf][0] - m01);
            float e1 = exp2f(s[nf][1] - m01);
            float e2 = exp2f(s[nf][2] - m23);
            float e3 = exp2f(s[nf][3] - m23);
            s[nf][0] = e0; s[nf][1] = e1; s[nf][2] = e2; s[nf][3] = e3;
            sum01 += e0 + e1;
            sum23 += e2 + e3;
        }
        sum01 += __shfl_xor_sync(0xffffffffu, sum01, 1);
        sum01 += __shfl_xor_sync(0xffffffffu, sum01, 2);
        sum23 += __shfl_xor_sync(0xffffffffu, sum23, 1);
        sum23 += __shfl_xor_sync(0xffffffffu, sum23, 2);
        l01 = l01 * cor01 + sum01;
        l23 = l23 * cor23 + sum23;

        // PV over this chunk's 64 k-rows
#pragma unroll
        for (int kj = 0; kj < 4; kj++) {
            int f0 = 2 * kj, f1 = 2 * kj + 1;
            uint32_t ph[4];
            ph[0] = packh2(s[f0][0], s[f0][1]);
            ph[1] = packh2(s[f0][2], s[f0][3]);
            ph[2] = packh2(s[f1][0], s[f1][1]);
            ph[3] = packh2(s[f1][2], s[f1][3]);
            int vrow = c0 + kj * 16 + l16;
#pragma unroll
            for (int dh2 = 0; dh2 < 2; dh2++) {
                uint32_t vf[4];
                ldm_x4_t(vf, smem_u32(Vf + vrow * AST + dh2 * 16 + ((lane >> 4) << 3)));
                mma_f16(o[2 * dh2],     ph, vf[0], vf[1]);
                mma_f16(o[2 * dh2 + 1], ph, vf[2], vf[3]);
            }
        }
    }

    // ---- epilogue: normalize, fp16, scatter to original token rows ----
    float inv0 = 1.0f / l01, inv1 = 1.0f / l23;
    int r0 = m0 + (lane >> 2);
    int tok0 = toks[r0], tok1 = toks[r0 + 8];
    size_t ob0 = (size_t)(b * NN + tok0) * CC + h * DD + (lane & 3) * 2;
    size_t ob1 = (size_t)(b * NN + tok1) * CC + h * DD + (lane & 3) * 2;
#pragma unroll
    for (int nf = 0; nf < 4; nf++) {
        *(__half2*)(g_y + ob0 + nf * 8) = __floats2half2_rn(o[nf][0] * inv0, o[nf][1] * inv0);
        *(__half2*)(g_y + ob1 + nf * 8) = __floats2half2_rn(o[nf][2] * inv1, o[nf][3] * inv1);
    }
}

// ---------------- 4) projection: fp16 2-term MMA, cp.async double-buffered ----------------
// out = y(fp16) @ (Wh+Wl)^T + bias. 3 planes per stage: Af, Bh, Bl.
#define PST  40
#define PPL  (128 * PST)
#define PSTG (3 * PPL)
#define SMEM_PROJ_BYTES (2 * PSTG * 2)

__global__ void __launch_bounds__(256)
k_proj2(const float* __restrict__ bias, float* __restrict__ out) {
    __half* sm = (__half*)dynsm;

    int tid  = threadIdx.x;
    int lane = tid & 31;
    int warp = tid >> 5;
    int row0 = blockIdx.x * 128;
    int col0 = blockIdx.y * 128;
    int m_off = (warp & 3) * 32;
    int n_off = (warp >> 2) * 64;
    int l16 = lane & 15;

    int c0 = tid * 2;
    int rA0 = c0 >> 2, qA0 = (c0 & 3) * 8;
    int rA1 = (c0 + 1) >> 2, qA1 = ((c0 + 1) & 3) * 8;

    const __half* gA   = g_y + (size_t)row0 * CC;
    const __half* gB_h = g_w_hi + (size_t)col0 * CC;
    const __half* gB_l = g_w_lo + (size_t)col0 * CC;

    auto load_stage = [&](int st, int k0) {
        __half* Af = sm + st * PSTG;
        __half* Bh = Af + PPL;
        __half* Bl = Bh + PPL;
        cp16(Af + rA0 * PST + qA0, gA + (size_t)rA0 * CC + k0 + qA0);
        cp16(Af + rA1 * PST + qA1, gA + (size_t)rA1 * CC + k0 + qA1);
        cp16(Bh + rA0 * PST + qA0, gB_h + (size_t)rA0 * CC + k0 + qA0);
        cp16(Bh + rA1 * PST + qA1, gB_h + (size_t)rA1 * CC + k0 + qA1);
        cp16(Bl + rA0 * PST + qA0, gB_l + (size_t)rA0 * CC + k0 + qA0);
        cp16(Bl + rA1 * PST + qA1, gB_l + (size_t)rA1 * CC + k0 + qA1);
        CP_COMMIT();
    };

    float c[2][8][4];
#pragma unroll
    for (int mf = 0; mf < 2; mf++)
#pragma unroll
        for (int nf = 0; nf < 8; nf++)
#pragma unroll
            for (int r = 0; r < 4; r++) c[mf][nf][r] = 0.0f;

    load_stage(0, 0);

    for (int kt = 0; kt < 8; kt++) {
        if (kt + 1 < 8) {
            load_stage((kt + 1) & 1, (kt + 1) * 32);
            CP_WAIT(1);
        } else {
            CP_WAIT(0);
        }
        __syncthreads();

        __half* Af = sm + (kt & 1) * PSTG;
        __half* Bh = Af + PPL;
        __half* Bl = Bh + PPL;

#pragma unroll
        for (int kk = 0; kk < 32; kk += 16) {
            uint32_t bh[8][2], bl[8][2];
#pragma unroll
            for (int np = 0; np < 4; np++) {
                uint32_t t4[4];
                int brow = n_off + np * 16 + ((lane >> 4) << 3) + (lane & 7);
                int bcol = kk + ((lane >> 3) & 1) * 8;
                ldm_x4(t4, smem_u32(Bh + brow * PST + bcol));
                bh[2 * np][0] = t4[0]; bh[2 * np][1] = t4[1];
                bh[2 * np + 1][0] = t4[2]; bh[2 * np + 1][1] = t4[3];
                ldm_x4(t4, smem_u32(Bl + brow * PST + bcol));
                bl[2 * np][0] = t4[0]; bl[2 * np][1] = t4[1];
                bl[2 * np + 1][0] = t4[2]; bl[2 * np + 1][1] = t4[3];
            }
#pragma unroll
            for (int mf = 0; mf < 2; mf++) {
                uint32_t af[4];
                int arow = m_off + mf * 16 + l16;
                ldm_x4(af, smem_u32(Af + arow * PST + kk + (lane >> 4) * 8));
#pragma unroll
                for (int nf = 0; nf < 8; nf++) {
                    mma_f16(c[mf][nf], af, bh[nf][0], bh[nf][1]);
                    mma_f16(c[mf][nf], af, bl[nf][0], bl[nf][1]);
                }
            }
        }
        __syncthreads();
    }

#pragma unroll
    for (int mf = 0; mf < 2; mf++) {
#pragma unroll
        for (int nf = 0; nf < 8; nf++) {
            int rg = row0 + m_off + mf * 16 + (lane >> 2);
            int cg = col0 + n_off + nf * 8 + (lane & 3) * 2;
            float b0 = bias[cg], b1 = bias[cg + 1];
            float2* o0 = (float2*)(out + (size_t)rg * CC + cg);
            float2* o1 = (float2*)(out + (size_t)(rg + 8) * CC + cg);
            *o0 = make_float2(c[mf][nf][0] + b0, c[mf][nf][1] + b1);
            *o1 = make_float2(c[mf][nf][2] + b0, c[mf][nf][3] + b1);
        }
    }
}

// ---------------- launch ----------------
extern "C" void kernel_launch(void* const* d_in, const int* in_sizes, int n_in,
                              void* d_out, int out_size) {
    const float* qkv         = (const float*)d_in[0];
    const float* sim         = (const float*)d_in[1];
    const float* proj_w      = (const float*)d_in[2];
    const float* proj_b      = (const float*)d_in[3];
    const float* logit_scale = (const float*)d_in[4];
    float* out = (float*)d_out;

    k_argmax_hist<<<BB * NCH, CHSZ>>>(sim, proj_w);
    k_scan<<<BB, 256>>>();
    k_scatter_par<<<BB * NCH, CHSZ>>>();

    // h fastest: 8 sibling head-blocks of one (b,g) co-run and share token rows in L2
    cudaFuncSetAttribute(k_attn_mma, cudaFuncAttributeMaxDynamicSharedMemorySize, SMEM_ATT_BYTES);
    k_attn_mma<<<dim3(HH, NG, BB), 256, SMEM_ATT_BYTES>>>(qkv, logit_scale);

    cudaFuncSetAttribute(k_proj2, cudaFuncAttributeMaxDynamicSharedMemorySize, SMEM_PROJ_BYTES);
    k_proj2<<<dim3((BB * NN) / 128, CC / 128), 256, SMEM_PROJ_BYTES>>>(proj_b, out);
}

// round 11
// speedup vs baseline: 1.3486x; 1.0461x over previous
#include <cuda_runtime.h>
#include <cuda_bf16.h>
#include <cuda_fp16.h>
#include <math.h>
#include <stdint.h>

// Problem constants (fixed by the benchmark shapes)
#define BB   4
#define NN   16384
#define CC   256
#define C3   768
#define TT   64
#define HH   8
#define DD   32
#define GS   128
#define NG   128
#define NCH  128
#define CHSZ 128

// -------- scratch (device globals) --------
__device__ int   g_tkid[BB * NN];
__device__ int   g_sortidx[BB * NN];
__device__ int   g_hist[BB * TT * NCH];
__device__ __half g_y[(size_t)BB * NN * CC];     // attention out, single fp16 plane
__device__ __half g_w_hi[CC * CC];               // W split fp16 planes
__device__ __half g_w_lo[CC * CC];

// ---------------- PTX helpers ----------------
__device__ __forceinline__ uint32_t smem_u32(const void* p) {
    return (uint32_t)__cvta_generic_to_shared(p);
}
__device__ __forceinline__ void ldm_x4(uint32_t* r, uint32_t a) {
    asm volatile("ldmatrix.sync.aligned.m8n8.x4.shared.b16 {%0,%1,%2,%3},[%4];"
                 : "=r"(r[0]), "=r"(r[1]), "=r"(r[2]), "=r"(r[3]) : "r"(a));
}
__device__ __forceinline__ void ldm_x4_t(uint32_t* r, uint32_t a) {
    asm volatile("ldmatrix.sync.aligned.m8n8.x4.trans.shared.b16 {%0,%1,%2,%3},[%4];"
                 : "=r"(r[0]), "=r"(r[1]), "=r"(r[2]), "=r"(r[3]) : "r"(a));
}
__device__ __forceinline__ void mma_bf16(float* c, const uint32_t* a, uint32_t b0, uint32_t b1) {
    asm volatile(
        "mma.sync.aligned.m16n8k16.row.col.f32.bf16.bf16.f32 "
        "{%0,%1,%2,%3},{%4,%5,%6,%7},{%8,%9},{%0,%1,%2,%3};"
        : "+f"(c[0]), "+f"(c[1]), "+f"(c[2]), "+f"(c[3])
        : "r"(a[0]), "r"(a[1]), "r"(a[2]), "r"(a[3]), "r"(b0), "r"(b1));
}
__device__ __forceinline__ void mma_f16(float* c, const uint32_t* a, uint32_t b0, uint32_t b1) {
    asm volatile(
        "mma.sync.aligned.m16n8k16.row.col.f32.f16.f16.f32 "
        "{%0,%1,%2,%3},{%4,%5,%6,%7},{%8,%9},{%0,%1,%2,%3};"
        : "+f"(c[0]), "+f"(c[1]), "+f"(c[2]), "+f"(c[3])
        : "r"(a[0]), "r"(a[1]), "r"(a[2]), "r"(a[3]), "r"(b0), "r"(b1));
}
__device__ __forceinline__ uint32_t packh2(float x, float y) {
    __half2 t = __floats2half2_rn(x, y);
    return *(uint32_t*)&t;
}
__device__ __forceinline__ void cp16(void* smem_dst, const void* gsrc) {
    asm volatile("cp.async.cg.shared.global [%0], [%1], 16;"
                 :: "r"(smem_u32(smem_dst)), "l"(gsrc));
}
#define CP_COMMIT()  asm volatile("cp.async.commit_group;")
#define CP_WAIT(N)   asm volatile("cp.async.wait_group %0;" :: "n"(N))

extern __shared__ __align__(16) char dynsm[];

// ---------------- 1+2a) fused argmax + histogram + W split (fp16) ----------------
__global__ void k_argmax_hist(const float* __restrict__ sim, const float* __restrict__ W) {
    __shared__ int h[TT];
    int b  = blockIdx.x / NCH;
    int ch = blockIdx.x % NCH;
    int t  = threadIdx.x;
    {
        int wi = blockIdx.x * CHSZ + t;
        float v = W[wi];
        __half hi = __float2half_rn(v);
        g_w_hi[wi] = hi;
        g_w_lo[wi] = __float2half_rn(v - __half2float(hi));
    }
    if (t < TT) h[t] = 0;
    int idx = b * NN + ch * CHSZ + t;
    const float4* p = (const float4*)(sim + (size_t)idx * TT);
    float best = -3.402823466e38f;
    int bi = 0;
#pragma unroll
    for (int i = 0; i < 16; i++) {
        float4 v = p[i];
        if (v.x > best) { best = v.x; bi = 4 * i + 0; }
        if (v.y > best) { best = v.y; bi = 4 * i + 1; }
        if (v.z > best) { best = v.z; bi = 4 * i + 2; }
        if (v.w > best) { best = v.w; bi = 4 * i + 3; }
    }
    g_tkid[idx] = bi;
    __syncthreads();
    atomicAdd(&h[bi], 1);
    __syncthreads();
    if (t < TT)
        g_hist[(b * TT + t) * NCH + ch] = h[t];
}

// ---------------- 2b) exclusive scan ----------------
__global__ void k_scan() {
    __shared__ int tot[256];
    int b = blockIdx.x;
    int* base = g_hist + b * TT * NCH;
    int t = threadIdx.x;
    int v[32];
    int s = 0;
#pragma unroll
    for (int i = 0; i < 32; i++) { v[i] = base[t * 32 + i]; s += v[i]; }
    tot[t] = s;
    __syncthreads();
    if (t == 0) {
        int acc = 0;
        for (int i = 0; i < 256; i++) { int x = tot[i]; tot[i] = acc; acc += x; }
    }
    __syncthreads();
    int ex = tot[t];
#pragma unroll
    for (int i = 0; i < 32; i++) { int x = v[i]; base[t * 32 + i] = ex; ex += x; }
}

// ---------------- 2c) parallel stable scatter ----------------
__global__ void k_scatter_par() {
    __shared__ int whist[4][TT];
    int b  = blockIdx.x / NCH;
    int ch = blockIdx.x % NCH;
    int t  = threadIdx.x;
    int lane = t & 31, w = t >> 5;
    ((int*)whist)[t] = 0;
    ((int*)whist)[t + 128] = 0;
    int key = g_tkid[b * NN + ch * CHSZ + t];
    __syncthreads();
    unsigned mask = __match_any_sync(0xffffffffu, key);
    int wrank = __popc(mask & ((1u << lane) - 1u));
    if (lane == (__ffs(mask) - 1))
        whist[w][key] = __popc(mask);
    __syncthreads();
    int off = 0;
#pragma unroll
    for (int w2 = 0; w2 < 3; w2++)
        if (w2 < w) off += whist[w2][key];
    int pos = g_hist[(b * TT + key) * NCH + ch] + off + wrank;
    g_sortidx[b * NN + pos] = ch * CHSZ + t;
}

// ---------------- 3) tensor-core attention, flash-chunked ----------------
// Grid = (HH, NG, BB): h fastest so sibling head-blocks co-run and tile each
// token's contiguous 3KB row across L2.
// Gather: wavefront-minimal — 8 lanes cover one 128B token-slice per LDG
// (1 L1 wavefront per line; 384 wf/CTA vs 1536 in the strided form).
// QK: bf16x3. PV: fp16. Output y: single fp16 plane.
#define AST 40
#define SM_Q_HI 0
#define SM_Q_LO (128 * AST)
#define SM_K_HI (2 * 128 * AST)
#define SM_K_LO (3 * 128 * AST)
#define SM_VF   (4 * 128 * AST)
#define SM_TOK  (5 * 128 * AST)
#define SMEM_ATT_BYTES (5 * 128 * AST * 2 + 128 * 4)

__global__ void __launch_bounds__(256, 3)
k_attn_mma(const float* __restrict__ qkv, const float* __restrict__ logit_scale) {
    __nv_bfloat16* sm = (__nv_bfloat16*)dynsm;
    __nv_bfloat16* Qh = sm + SM_Q_HI;
    __nv_bfloat16* Ql = sm + SM_Q_LO;
    __nv_bfloat16* Kh = sm + SM_K_HI;
    __nv_bfloat16* Kl = sm + SM_K_LO;
    __half*        Vf = (__half*)(sm + SM_VF);
    int* toks = (int*)(sm + SM_TOK);

    int h = blockIdx.x, g = blockIdx.y, b = blockIdx.z;
    int tid = threadIdx.x, lane = tid & 31, warp = tid >> 5;

    // ---- stage sorted token ids ----
    if (tid < GS) toks[tid] = g_sortidx[b * NN + g * GS + tid];
    __syncthreads();

    // ---- wavefront-minimal gather ----
    // lane group: row = i2*32 + (tid>>3), sub = tid&7 (16B unit within 128B slice).
    // 8 consecutive lanes cover one full 128B line per LDG.
    {
        const float* qb = qkv + (size_t)b * NN * C3 + h * DD;
        int rsub  = tid & 7;
        int rbase = tid >> 3;                       // 0..31
#pragma unroll
        for (int tsel = 0; tsel < 3; tsel++) {
            // batch the 4 row addresses then 4 independent LDGs (MLP>=4)
            int rw[4];
            const float4* ap[4];
#pragma unroll
            for (int i2 = 0; i2 < 4; i2++) {
                rw[i2] = i2 * 32 + rbase;
                ap[i2] = (const float4*)(qb + (size_t)toks[rw[i2]] * C3 + tsel * CC + rsub * 4);
            }
#pragma unroll
            for (int i2 = 0; i2 < 4; i2++) {
                float4 x = *ap[i2];
                int row = rw[i2];
                if (tsel < 2) {
                    __nv_bfloat162 h01 = __floats2bfloat162_rn(x.x, x.y);
                    __nv_bfloat162 h23 = __floats2bfloat162_rn(x.z, x.w);
                    float2 f01 = __bfloat1622float2(h01);
                    float2 f23 = __bfloat1622float2(h23);
                    __nv_bfloat162 l01 = __floats2bfloat162_rn(x.x - f01.x, x.y - f01.y);
                    __nv_bfloat162 l23 = __floats2bfloat162_rn(x.z - f23.x, x.w - f23.y);
                    __nv_bfloat16* dh = (tsel == 0 ? Qh : Kh) + row * AST + rsub * 4;
                    __nv_bfloat16* dl = (tsel == 0 ? Ql : Kl) + row * AST + rsub * 4;
                    *(uint2*)dh = make_uint2(*(uint32_t*)&h01, *(uint32_t*)&h23);
                    *(uint2*)dl = make_uint2(*(uint32_t*)&l01, *(uint32_t*)&l23);
                } else {
                    __half2 p01 = __floats2half2_rn(x.x, x.y);
                    __half2 p23 = __floats2half2_rn(x.z, x.w);
                    *(uint2*)(Vf + row * AST + rsub * 4) =
                        make_uint2(*(uint32_t*)&p01, *(uint32_t*)&p23);
                }
            }
        }
    }
    // fold softmax scale and log2(e): p = exp2(s*sc2 - M2)
    float sc2 = __expf(fminf(logit_scale[0], 4.605170185988091f)) * 1.44269504088896f;
    __syncthreads();

    int m0 = warp * 16;
    int l16 = lane & 15;

    uint32_t qh[2][4];
#pragma unroll
    for (int ks = 0; ks < 2; ks++)
        ldm_x4(qh[ks], smem_u32(Qh + (m0 + l16) * AST + ks * 16 + (lane >> 4) * 8));

    float o[4][4];
#pragma unroll
    for (int nf = 0; nf < 4; nf++)
#pragma unroll
        for (int r = 0; r < 4; r++) o[nf][r] = 0.0f;
    float m01 = -1e30f, m23 = -1e30f, l01 = 0.0f, l23 = 0.0f;

#pragma unroll
    for (int chnk = 0; chnk < 2; chnk++) {
        int c0 = chnk * 64;
        uint32_t ql[2][4];
#pragma unroll
        for (int ks = 0; ks < 2; ks++)
            ldm_x4(ql[ks], smem_u32(Ql + (m0 + l16) * AST + ks * 16 + (lane >> 4) * 8));

        float s[8][4];
#pragma unroll
        for (int nf = 0; nf < 8; nf++)
#pragma unroll
            for (int r = 0; r < 4; r++) s[nf][r] = 0.0f;

#pragma unroll
        for (int p2 = 0; p2 < 4; p2++) {
            int j0 = c0 + p2 * 16;
#pragma unroll
            for (int ks = 0; ks < 2; ks++) {
                uint32_t kb[4], kl4[4];
                int krow = j0 + ((lane >> 4) << 3) + (lane & 7);
                int kcol = ks * 16 + ((lane >> 3) & 1) * 8;
                ldm_x4(kb,  smem_u32(Kh + krow * AST + kcol));
                ldm_x4(kl4, smem_u32(Kl + krow * AST + kcol));
                mma_bf16(s[2 * p2],     qh[ks], kb[0],  kb[1]);
                mma_bf16(s[2 * p2],     qh[ks], kl4[0], kl4[1]);
                mma_bf16(s[2 * p2],     ql[ks], kb[0],  kb[1]);
                mma_bf16(s[2 * p2 + 1], qh[ks], kb[2],  kb[3]);
                mma_bf16(s[2 * p2 + 1], qh[ks], kl4[2], kl4[3]);
                mma_bf16(s[2 * p2 + 1], ql[ks], kb[2],  kb[3]);
            }
        }

        // scale fold + chunk row-max (quad shfl)
        float cm01 = -1e30f, cm23 = -1e30f;
#pragma unroll
        for (int nf = 0; nf < 8; nf++) {
#pragma unroll
            for (int r = 0; r < 4; r++) s[nf][r] *= sc2;
            cm01 = fmaxf(cm01, fmaxf(s[nf][0], s[nf][1]));
            cm23 = fmaxf(cm23, fmaxf(s[nf][2], s[nf][3]));
        }
        cm01 = fmaxf(cm01, __shfl_xor_sync(0xffffffffu, cm01, 1));
        cm01 = fmaxf(cm01, __shfl_xor_sync(0xffffffffu, cm01, 2));
        cm23 = fmaxf(cm23, __shfl_xor_sync(0xffffffffu, cm23, 1));
        cm23 = fmaxf(cm23, __shfl_xor_sync(0xffffffffu, cm23, 2));

        // online update
        float nm01 = fmaxf(m01, cm01), nm23 = fmaxf(m23, cm23);
        float cor01 = exp2f(m01 - nm01), cor23 = exp2f(m23 - nm23);
        m01 = nm01; m23 = nm23;
#pragma unroll
        for (int nf = 0; nf < 4; nf++) {
            o[nf][0] *= cor01; o[nf][1] *= cor01;
            o[nf][2] *= cor23; o[nf][3] *= cor23;
        }

        float sum01 = 0.0f, sum23 = 0.0f;
#pragma unroll
        for (int nf = 0; nf < 8; nf++) {
            float e0 = exp2f(s[nf][0] - m01);
            float e1 = exp2f(s[nf][1] - m01);
            float e2 = exp2f(s[nf][2] - m23);
            float e3 = exp2f(s[nf][3] - m23);
            s[nf][0] = e0; s[nf][1] = e1; s[nf][2] = e2; s[nf][3] = e3;
            sum01 += e0 + e1;
            sum23 += e2 + e3;
        }
        sum01 += __shfl_xor_sync(0xffffffffu, sum01, 1);
        sum01 += __shfl_xor_sync(0xffffffffu, sum01, 2);
        sum23 += __shfl_xor_sync(0xffffffffu, sum23, 1);
        sum23 += __shfl_xor_sync(0xffffffffu, sum23, 2);
        l01 = l01 * cor01 + sum01;
        l23 = l23 * cor23 + sum23;

        // PV over this chunk's 64 k-rows
#pragma unroll
        for (int kj = 0; kj < 4; kj++) {
            int f0 = 2 * kj, f1 = 2 * kj + 1;
            uint32_t ph[4];
            ph[0] = packh2(s[f0][0], s[f0][1]);
            ph[1] = packh2(s[f0][2], s[f0][3]);
            ph[2] = packh2(s[f1][0], s[f1][1]);
            ph[3] = packh2(s[f1][2], s[f1][3]);
            int vrow = c0 + kj * 16 + l16;
#pragma unroll
            for (int dh2 = 0; dh2 < 2; dh2++) {
                uint32_t vf[4];
                ldm_x4_t(vf, smem_u32(Vf + vrow * AST + dh2 * 16 + ((lane >> 4) << 3)));
                mma_f16(o[2 * dh2],     ph, vf[0], vf[1]);
                mma_f16(o[2 * dh2 + 1], ph, vf[2], vf[3]);
            }
        }
    }

    // ---- epilogue: normalize, fp16, scatter to original token rows ----
    float inv0 = 1.0f / l01, inv1 = 1.0f / l23;
    int r0 = m0 + (lane >> 2);
    int tok0 = toks[r0], tok1 = toks[r0 + 8];
    size_t ob0 = (size_t)(b * NN + tok0) * CC + h * DD + (lane & 3) * 2;
    size_t ob1 = (size_t)(b * NN + tok1) * CC + h * DD + (lane & 3) * 2;
#pragma unroll
    for (int nf = 0; nf < 4; nf++) {
        *(__half2*)(g_y + ob0 + nf * 8) = __floats2half2_rn(o[nf][0] * inv0, o[nf][1] * inv0);
        *(__half2*)(g_y + ob1 + nf * 8) = __floats2half2_rn(o[nf][2] * inv1, o[nf][3] * inv1);
    }
}

// ---------------- 4) projection: fp16 2-term MMA, cp.async double-buffered ----------------
#define PST  40
#define PPL  (128 * PST)
#define PSTG (3 * PPL)
#define SMEM_PROJ_BYTES (2 * PSTG * 2)

__global__ void __launch_bounds__(256)
k_proj2(const float* __restrict__ bias, float* __restrict__ out) {
    __half* sm = (__half*)dynsm;

    int tid  = threadIdx.x;
    int lane = tid & 31;
    int warp = tid >> 5;
    int row0 = blockIdx.x * 128;
    int col0 = blockIdx.y * 128;
    int m_off = (warp & 3) * 32;
    int n_off = (warp >> 2) * 64;
    int l16 = lane & 15;

    int c0 = tid * 2;
    int rA0 = c0 >> 2, qA0 = (c0 & 3) * 8;
    int rA1 = (c0 + 1) >> 2, qA1 = ((c0 + 1) & 3) * 8;

    const __half* gA   = g_y + (size_t)row0 * CC;
    const __half* gB_h = g_w_hi + (size_t)col0 * CC;
    const __half* gB_l = g_w_lo + (size_t)col0 * CC;

    auto load_stage = [&](int st, int k0) {
        __half* Af = sm + st * PSTG;
        __half* Bh = Af + PPL;
        __half* Bl = Bh + PPL;
        cp16(Af + rA0 * PST + qA0, gA + (size_t)rA0 * CC + k0 + qA0);
        cp16(Af + rA1 * PST + qA1, gA + (size_t)rA1 * CC + k0 + qA1);
        cp16(Bh + rA0 * PST + qA0, gB_h + (size_t)rA0 * CC + k0 + qA0);
        cp16(Bh + rA1 * PST + qA1, gB_h + (size_t)rA1 * CC + k0 + qA1);
        cp16(Bl + rA0 * PST + qA0, gB_l + (size_t)rA0 * CC + k0 + qA0);
        cp16(Bl + rA1 * PST + qA1, gB_l + (size_t)rA1 * CC + k0 + qA1);
        CP_COMMIT();
    };

    float c[2][8][4];
#pragma unroll
    for (int mf = 0; mf < 2; mf++)
#pragma unroll
        for (int nf = 0; nf < 8; nf++)
#pragma unroll
            for (int r = 0; r < 4; r++) c[mf][nf][r] = 0.0f;

    load_stage(0, 0);

    for (int kt = 0; kt < 8; kt++) {
        if (kt + 1 < 8) {
            load_stage((kt + 1) & 1, (kt + 1) * 32);
            CP_WAIT(1);
        } else {
            CP_WAIT(0);
        }
        __syncthreads();

        __half* Af = sm + (kt & 1) * PSTG;
        __half* Bh = Af + PPL;
        __half* Bl = Bh + PPL;

#pragma unroll
        for (int kk = 0; kk < 32; kk += 16) {
            uint32_t bh[8][2], bl[8][2];
#pragma unroll
            for (int np = 0; np < 4; np++) {
                uint32_t t4[4];
                int brow = n_off + np * 16 + ((lane >> 4) << 3) + (lane & 7);
                int bcol = kk + ((lane >> 3) & 1) * 8;
                ldm_x4(t4, smem_u32(Bh + brow * PST + bcol));
                bh[2 * np][0] = t4[0]; bh[2 * np][1] = t4[1];
                bh[2 * np + 1][0] = t4[2]; bh[2 * np + 1][1] = t4[3];
                ldm_x4(t4, smem_u32(Bl + brow * PST + bcol));
                bl[2 * np][0] = t4[0]; bl[2 * np][1] = t4[1];
                bl[2 * np + 1][0] = t4[2]; bl[2 * np + 1][1] = t4[3];
            }
#pragma unroll
            for (int mf = 0; mf < 2; mf++) {
                uint32_t af[4];
                int arow = m_off + mf * 16 + l16;
                ldm_x4(af, smem_u32(Af + arow * PST + kk + (lane >> 4) * 8));
#pragma unroll
                for (int nf = 0; nf < 8; nf++) {
                    mma_f16(c[mf][nf], af, bh[nf][0], bh[nf][1]);
                    mma_f16(c[mf][nf], af, bl[nf][0], bl[nf][1]);
                }
            }
        }
        __syncthreads();
    }

#pragma unroll
    for (int mf = 0; mf < 2; mf++) {
#pragma unroll
        for (int nf = 0; nf < 8; nf++) {
            int rg = row0 + m_off + mf * 16 + (lane >> 2);
            int cg = col0 + n_off + nf * 8 + (lane & 3) * 2;
            float b0 = bias[cg], b1 = bias[cg + 1];
            float2* o0 = (float2*)(out + (size_t)rg * CC + cg);
            float2* o1 = (float2*)(out + (size_t)(rg + 8) * CC + cg);
            *o0 = make_float2(c[mf][nf][0] + b0, c[mf][nf][1] + b1);
            *o1 = make_float2(c[mf][nf][2] + b0, c[mf][nf][3] + b1);
        }
    }
}

// ---------------- launch ----------------
extern "C" void kernel_launch(void* const* d_in, const int* in_sizes, int n_in,
                              void* d_out, int out_size) {
    const float* qkv         = (const float*)d_in[0];
    const float* sim         = (const float*)d_in[1];
    const float* proj_w      = (const float*)d_in[2];
    const float* proj_b      = (const float*)d_in[3];
    const float* logit_scale = (const float*)d_in[4];
    float* out = (float*)d_out;

    k_argmax_hist<<<BB * NCH, CHSZ>>>(sim, proj_w);
    k_scan<<<BB, 256>>>();
    k_scatter_par<<<BB * NCH, CHSZ>>>();

    // h fastest: 8 sibling head-blocks of one (b,g) co-run and share token rows in L2
    cudaFuncSetAttribute(k_attn_mma, cudaFuncAttributeMaxDynamicSharedMemorySize, SMEM_ATT_BYTES);
    k_attn_mma<<<dim3(HH, NG, BB), 256, SMEM_ATT_BYTES>>>(qkv, logit_scale);

    cudaFuncSetAttribute(k_proj2, cudaFuncAttributeMaxDynamicSharedMemorySize, SMEM_PROJ_BYTES);
    k_proj2<<<dim3((BB * NN) / 128, CC / 128), 256, SMEM_PROJ_BYTES>>>(proj_b, out);
}

// round 12
// speedup vs baseline: 1.4252x; 1.0568x over previous
#include <cuda_runtime.h>
#include <cuda_bf16.h>
#include <cuda_fp16.h>
#include <math.h>
#include <stdint.h>

// Problem constants (fixed by the benchmark shapes)
#define BB   4
#define NN   16384
#define CC   256
#define C3   768
#define TT   64
#define HH   8
#define DD   32
#define GS   128
#define NG   128
#define NCH  128
#define CHSZ 128

// -------- scratch (device globals) --------
__device__ int   g_tkid[BB * NN];
__device__ int   g_sortidx[BB * NN];
__device__ int   g_hist[BB * TT * NCH];
__device__ __half g_y[(size_t)BB * NN * CC];     // attention out, single fp16 plane
__device__ __half g_w[CC * CC];                  // W fp16 (1-term)

// ---------------- PTX helpers ----------------
__device__ __forceinline__ uint32_t smem_u32(const void* p) {
    return (uint32_t)__cvta_generic_to_shared(p);
}
__device__ __forceinline__ void ldm_x4(uint32_t* r, uint32_t a) {
    asm volatile("ldmatrix.sync.aligned.m8n8.x4.shared.b16 {%0,%1,%2,%3},[%4];"
                 : "=r"(r[0]), "=r"(r[1]), "=r"(r[2]), "=r"(r[3]) : "r"(a));
}
__device__ __forceinline__ void ldm_x4_t(uint32_t* r, uint32_t a) {
    asm volatile("ldmatrix.sync.aligned.m8n8.x4.trans.shared.b16 {%0,%1,%2,%3},[%4];"
                 : "=r"(r[0]), "=r"(r[1]), "=r"(r[2]), "=r"(r[3]) : "r"(a));
}
__device__ __forceinline__ void mma_bf16(float* c, const uint32_t* a, uint32_t b0, uint32_t b1) {
    asm volatile(
        "mma.sync.aligned.m16n8k16.row.col.f32.bf16.bf16.f32 "
        "{%0,%1,%2,%3},{%4,%5,%6,%7},{%8,%9},{%0,%1,%2,%3};"
        : "+f"(c[0]), "+f"(c[1]), "+f"(c[2]), "+f"(c[3])
        : "r"(a[0]), "r"(a[1]), "r"(a[2]), "r"(a[3]), "r"(b0), "r"(b1));
}
__device__ __forceinline__ void mma_f16(float* c, const uint32_t* a, uint32_t b0, uint32_t b1) {
    asm volatile(
        "mma.sync.aligned.m16n8k16.row.col.f32.f16.f16.f32 "
        "{%0,%1,%2,%3},{%4,%5,%6,%7},{%8,%9},{%0,%1,%2,%3};"
        : "+f"(c[0]), "+f"(c[1]), "+f"(c[2]), "+f"(c[3])
        : "r"(a[0]), "r"(a[1]), "r"(a[2]), "r"(a[3]), "r"(b0), "r"(b1));
}
__device__ __forceinline__ uint32_t packh2(float x, float y) {
    __half2 t = __floats2half2_rn(x, y);
    return *(uint32_t*)&t;
}
__device__ __forceinline__ void cp16(void* smem_dst, const void* gsrc) {
    asm volatile("cp.async.cg.shared.global [%0], [%1], 16;"
                 :: "r"(smem_u32(smem_dst)), "l"(gsrc));
}
#define CP_COMMIT()  asm volatile("cp.async.commit_group;")
#define CP_WAIT(N)   asm volatile("cp.async.wait_group %0;" :: "n"(N))

extern __shared__ __align__(16) char dynsm[];

// ---------------- 1+2a) fused argmax + histogram + W fp16 convert ----------------
__global__ void k_argmax_hist(const float* __restrict__ sim, const float* __restrict__ W) {
    __shared__ int h[TT];
    int b  = blockIdx.x / NCH;
    int ch = blockIdx.x % NCH;
    int t  = threadIdx.x;
    {
        int wi = blockIdx.x * CHSZ + t;
        g_w[wi] = __float2half_rn(W[wi]);
    }
    if (t < TT) h[t] = 0;
    int idx = b * NN + ch * CHSZ + t;
    const float4* p = (const float4*)(sim + (size_t)idx * TT);
    float best = -3.402823466e38f;
    int bi = 0;
#pragma unroll
    for (int i = 0; i < 16; i++) {
        float4 v = p[i];
        if (v.x > best) { best = v.x; bi = 4 * i + 0; }
        if (v.y > best) { best = v.y; bi = 4 * i + 1; }
        if (v.z > best) { best = v.z; bi = 4 * i + 2; }
        if (v.w > best) { best = v.w; bi = 4 * i + 3; }
    }
    g_tkid[idx] = bi;
    __syncthreads();
    atomicAdd(&h[bi], 1);
    __syncthreads();
    if (t < TT)
        g_hist[(b * TT + t) * NCH + ch] = h[t];
}

// ---------------- 2b) exclusive scan ----------------
__global__ void k_scan() {
    __shared__ int tot[256];
    int b = blockIdx.x;
    int* base = g_hist + b * TT * NCH;
    int t = threadIdx.x;
    int v[32];
    int s = 0;
#pragma unroll
    for (int i = 0; i < 32; i++) { v[i] = base[t * 32 + i]; s += v[i]; }
    tot[t] = s;
    __syncthreads();
    if (t == 0) {
        int acc = 0;
        for (int i = 0; i < 256; i++) { int x = tot[i]; tot[i] = acc; acc += x; }
    }
    __syncthreads();
    int ex = tot[t];
#pragma unroll
    for (int i = 0; i < 32; i++) { int x = v[i]; base[t * 32 + i] = ex; ex += x; }
}

// ---------------- 2c) parallel stable scatter ----------------
__global__ void k_scatter_par() {
    __shared__ int whist[4][TT];
    int b  = blockIdx.x / NCH;
    int ch = blockIdx.x % NCH;
    int t  = threadIdx.x;
    int lane = t & 31, w = t >> 5;
    ((int*)whist)[t] = 0;
    ((int*)whist)[t + 128] = 0;
    int key = g_tkid[b * NN + ch * CHSZ + t];
    __syncthreads();
    unsigned mask = __match_any_sync(0xffffffffu, key);
    int wrank = __popc(mask & ((1u << lane) - 1u));
    if (lane == (__ffs(mask) - 1))
        whist[w][key] = __popc(mask);
    __syncthreads();
    int off = 0;
#pragma unroll
    for (int w2 = 0; w2 < 3; w2++)
        if (w2 < w) off += whist[w2][key];
    int pos = g_hist[(b * TT + key) * NCH + ch] + off + wrank;
    g_sortidx[b * NN + pos] = ch * CHSZ + t;
}

// ---------------- 3) tensor-core attention, 4 warps x 32 rows, flash 4x32 ----------------
// Grid = (HH, NG, BB): h fastest (sibling heads share token rows in L2).
// 128 threads = 4 warps; warp owns 32 rows (2 m-frags) -> K/V smem read volume
// halves vs 8-warp layout. Flash chunk = 32 cols (4 chunks) to bound registers.
// QK: bf16x3. PV: fp16. y: fp16.
#define AST 40
#define SM_Q_HI 0
#define SM_Q_LO (128 * AST)
#define SM_K_HI (2 * 128 * AST)
#define SM_K_LO (3 * 128 * AST)
#define SM_VF   (4 * 128 * AST)
#define SM_TOK  (5 * 128 * AST)
#define SMEM_ATT_BYTES (5 * 128 * AST * 2 + 128 * 4)

__global__ void __launch_bounds__(128, 4)
k_attn_mma(const float* __restrict__ qkv, const float* __restrict__ logit_scale) {
    __nv_bfloat16* sm = (__nv_bfloat16*)dynsm;
    __nv_bfloat16* Qh = sm + SM_Q_HI;
    __nv_bfloat16* Ql = sm + SM_Q_LO;
    __nv_bfloat16* Kh = sm + SM_K_HI;
    __nv_bfloat16* Kl = sm + SM_K_LO;
    __half*        Vf = (__half*)(sm + SM_VF);
    int* toks = (int*)(sm + SM_TOK);

    int h = blockIdx.x, g = blockIdx.y, b = blockIdx.z;
    int tid = threadIdx.x, lane = tid & 31, warp = tid >> 5;   // warp 0..3

    // ---- stage sorted token ids ----
    toks[tid] = g_sortidx[b * NN + g * GS + tid];
    __syncthreads();

    // ---- wavefront-minimal gather: 8 lanes cover one 128B token-slice per LDG ----
    // rsub = tid&7 (16B unit), rbase = tid>>3 (0..15); rows = i*16 + rbase.
    {
        const float* qb = qkv + (size_t)b * NN * C3 + h * DD;
        int rsub  = tid & 7;
        int rbase = tid >> 3;
#pragma unroll
        for (int tsel = 0; tsel < 3; tsel++) {
#pragma unroll
            for (int hbat = 0; hbat < 2; hbat++) {
                int rw[4];
                const float4* ap[4];
#pragma unroll
                for (int j = 0; j < 4; j++) {
                    rw[j] = (hbat * 4 + j) * 16 + rbase;
                    ap[j] = (const float4*)(qb + (size_t)toks[rw[j]] * C3 + tsel * CC + rsub * 4);
                }
#pragma unroll
                for (int j = 0; j < 4; j++) {
                    float4 x = *ap[j];
                    int row = rw[j];
                    if (tsel < 2) {
                        __nv_bfloat162 h01 = __floats2bfloat162_rn(x.x, x.y);
                        __nv_bfloat162 h23 = __floats2bfloat162_rn(x.z, x.w);
                        float2 f01 = __bfloat1622float2(h01);
                        float2 f23 = __bfloat1622float2(h23);
                        __nv_bfloat162 l01 = __floats2bfloat162_rn(x.x - f01.x, x.y - f01.y);
                        __nv_bfloat162 l23 = __floats2bfloat162_rn(x.z - f23.x, x.w - f23.y);
                        __nv_bfloat16* dh = (tsel == 0 ? Qh : Kh) + row * AST + rsub * 4;
                        __nv_bfloat16* dl = (tsel == 0 ? Ql : Kl) + row * AST + rsub * 4;
                        *(uint2*)dh = make_uint2(*(uint32_t*)&h01, *(uint32_t*)&h23);
                        *(uint2*)dl = make_uint2(*(uint32_t*)&l01, *(uint32_t*)&l23);
                    } else {
                        __half2 p01 = __floats2half2_rn(x.x, x.y);
                        __half2 p23 = __floats2half2_rn(x.z, x.w);
                        *(uint2*)(Vf + row * AST + rsub * 4) =
                            make_uint2(*(uint32_t*)&p01, *(uint32_t*)&p23);
                    }
                }
            }
        }
    }
    // fold softmax scale and log2(e): p = exp2(s*sc2 - M2)
    float sc2 = __expf(fminf(logit_scale[0], 4.605170185988091f)) * 1.44269504088896f;
    __syncthreads();

    int m0 = warp * 32;
    int l16 = lane & 15;

    // Q hi fragments resident (2 m-frags x 2 k-steps)
    uint32_t qh[2][2][4];
#pragma unroll
    for (int mf = 0; mf < 2; mf++)
#pragma unroll
        for (int ks = 0; ks < 2; ks++)
            ldm_x4(qh[mf][ks],
                   smem_u32(Qh + (m0 + mf * 16 + l16) * AST + ks * 16 + (lane >> 4) * 8));

    float o[2][4][4];
#pragma unroll
    for (int mf = 0; mf < 2; mf++)
#pragma unroll
        for (int nf = 0; nf < 4; nf++)
#pragma unroll
            for (int r = 0; r < 4; r++) o[mf][nf][r] = 0.0f;
    float mrun[2][2], lrun[2][2];
#pragma unroll
    for (int mf = 0; mf < 2; mf++) {
        mrun[mf][0] = -1e30f; mrun[mf][1] = -1e30f;
        lrun[mf][0] = 0.0f;   lrun[mf][1] = 0.0f;
    }

#pragma unroll
    for (int chnk = 0; chnk < 4; chnk++) {
        int c0 = chnk * 32;
        uint32_t ql[2][2][4];
#pragma unroll
        for (int mf = 0; mf < 2; mf++)
#pragma unroll
            for (int ks = 0; ks < 2; ks++)
                ldm_x4(ql[mf][ks],
                       smem_u32(Ql + (m0 + mf * 16 + l16) * AST + ks * 16 + (lane >> 4) * 8));

        float s[2][4][4];
#pragma unroll
        for (int mf = 0; mf < 2; mf++)
#pragma unroll
            for (int nf = 0; nf < 4; nf++)
#pragma unroll
                for (int r = 0; r < 4; r++) s[mf][nf][r] = 0.0f;

#pragma unroll
        for (int p2 = 0; p2 < 2; p2++) {
            int j0 = c0 + p2 * 16;
#pragma unroll
            for (int ks = 0; ks < 2; ks++) {
                uint32_t kb[4], kl4[4];
                int krow = j0 + ((lane >> 4) << 3) + (lane & 7);
                int kcol = ks * 16 + ((lane >> 3) & 1) * 8;
                ldm_x4(kb,  smem_u32(Kh + krow * AST + kcol));
                ldm_x4(kl4, smem_u32(Kl + krow * AST + kcol));
#pragma unroll
                for (int mf = 0; mf < 2; mf++) {
                    mma_bf16(s[mf][2 * p2],     qh[mf][ks], kb[0],  kb[1]);
                    mma_bf16(s[mf][2 * p2],     qh[mf][ks], kl4[0], kl4[1]);
                    mma_bf16(s[mf][2 * p2],     ql[mf][ks], kb[0],  kb[1]);
                    mma_bf16(s[mf][2 * p2 + 1], qh[mf][ks], kb[2],  kb[3]);
                    mma_bf16(s[mf][2 * p2 + 1], qh[mf][ks], kl4[2], kl4[3]);
                    mma_bf16(s[mf][2 * p2 + 1], ql[mf][ks], kb[2],  kb[3]);
                }
            }
        }

        // scale fold + chunk row-max + online update (per m-frag, per half)
#pragma unroll
        for (int mf = 0; mf < 2; mf++) {
            float cm0 = -1e30f, cm1 = -1e30f;
#pragma unroll
            for (int nf = 0; nf < 4; nf++) {
#pragma unroll
                for (int r = 0; r < 4; r++) s[mf][nf][r] *= sc2;
                cm0 = fmaxf(cm0, fmaxf(s[mf][nf][0], s[mf][nf][1]));
                cm1 = fmaxf(cm1, fmaxf(s[mf][nf][2], s[mf][nf][3]));
            }
            cm0 = fmaxf(cm0, __shfl_xor_sync(0xffffffffu, cm0, 1));
            cm0 = fmaxf(cm0, __shfl_xor_sync(0xffffffffu, cm0, 2));
            cm1 = fmaxf(cm1, __shfl_xor_sync(0xffffffffu, cm1, 1));
            cm1 = fmaxf(cm1, __shfl_xor_sync(0xffffffffu, cm1, 2));

            float nm0 = fmaxf(mrun[mf][0], cm0), nm1 = fmaxf(mrun[mf][1], cm1);
            float cor0 = exp2f(mrun[mf][0] - nm0), cor1 = exp2f(mrun[mf][1] - nm1);
            mrun[mf][0] = nm0; mrun[mf][1] = nm1;
#pragma unroll
            for (int nf = 0; nf < 4; nf++) {
                o[mf][nf][0] *= cor0; o[mf][nf][1] *= cor0;
                o[mf][nf][2] *= cor1; o[mf][nf][3] *= cor1;
            }
            float sum0 = 0.0f, sum1 = 0.0f;
#pragma unroll
            for (int nf = 0; nf < 4; nf++) {
                float e0 = exp2f(s[mf][nf][0] - nm0);
                float e1 = exp2f(s[mf][nf][1] - nm0);
                float e2 = exp2f(s[mf][nf][2] - nm1);
                float e3 = exp2f(s[mf][nf][3] - nm1);
                s[mf][nf][0] = e0; s[mf][nf][1] = e1; s[mf][nf][2] = e2; s[mf][nf][3] = e3;
                sum0 += e0 + e1;
                sum1 += e2 + e3;
            }
            sum0 += __shfl_xor_sync(0xffffffffu, sum0, 1);
            sum0 += __shfl_xor_sync(0xffffffffu, sum0, 2);
            sum1 += __shfl_xor_sync(0xffffffffu, sum1, 1);
            sum1 += __shfl_xor_sync(0xffffffffu, sum1, 2);
            lrun[mf][0] = lrun[mf][0] * cor0 + sum0;
            lrun[mf][1] = lrun[mf][1] * cor1 + sum1;
        }

        // PV over this chunk's 32 k-rows
#pragma unroll
        for (int kj = 0; kj < 2; kj++) {
            int f0 = 2 * kj, f1 = 2 * kj + 1;
            uint32_t ph[2][4];
#pragma unroll
            for (int mf = 0; mf < 2; mf++) {
                ph[mf][0] = packh2(s[mf][f0][0], s[mf][f0][1]);
                ph[mf][1] = packh2(s[mf][f0][2], s[mf][f0][3]);
                ph[mf][2] = packh2(s[mf][f1][0], s[mf][f1][1]);
                ph[mf][3] = packh2(s[mf][f1][2], s[mf][f1][3]);
            }
            int vrow = c0 + kj * 16 + l16;
#pragma unroll
            for (int dh2 = 0; dh2 < 2; dh2++) {
                uint32_t vf[4];
                ldm_x4_t(vf, smem_u32(Vf + vrow * AST + dh2 * 16 + ((lane >> 4) << 3)));
#pragma unroll
                for (int mf = 0; mf < 2; mf++) {
                    mma_f16(o[mf][2 * dh2],     ph[mf], vf[0], vf[1]);
                    mma_f16(o[mf][2 * dh2 + 1], ph[mf], vf[2], vf[3]);
                }
            }
        }
    }

    // ---- epilogue: normalize, fp16, scatter to original token rows ----
#pragma unroll
    for (int mf = 0; mf < 2; mf++) {
        float inv0 = 1.0f / lrun[mf][0], inv1 = 1.0f / lrun[mf][1];
        int r0 = m0 + mf * 16 + (lane >> 2);
        int tok0 = toks[r0], tok1 = toks[r0 + 8];
        size_t ob0 = (size_t)(b * NN + tok0) * CC + h * DD + (lane & 3) * 2;
        size_t ob1 = (size_t)(b * NN + tok1) * CC + h * DD + (lane & 3) * 2;
#pragma unroll
        for (int nf = 0; nf < 4; nf++) {
            *(__half2*)(g_y + ob0 + nf * 8) =
                __floats2half2_rn(o[mf][nf][0] * inv0, o[mf][nf][1] * inv0);
            *(__half2*)(g_y + ob1 + nf * 8) =
                __floats2half2_rn(o[mf][nf][2] * inv1, o[mf][nf][3] * inv1);
        }
    }
}

// ---------------- 4) projection: fp16 1-term MMA, cp.async double-buffered ----------------
// out = y(fp16) @ W(fp16)^T + bias. 2 planes per stage: Af, Bf.
#define PST  40
#define PPL  (128 * PST)
#define PSTG (2 * PPL)
#define SMEM_PROJ_BYTES (2 * PSTG * 2)

__global__ void __launch_bounds__(256)
k_proj2(const float* __restrict__ bias, float* __restrict__ out) {
    __half* sm = (__half*)dynsm;

    int tid  = threadIdx.x;
    int lane = tid & 31;
    int warp = tid >> 5;
    int row0 = blockIdx.x * 128;
    int col0 = blockIdx.y * 128;
    int m_off = (warp & 3) * 32;
    int n_off = (warp >> 2) * 64;
    int l16 = lane & 15;

    int c0 = tid * 2;
    int rA0 = c0 >> 2, qA0 = (c0 & 3) * 8;
    int rA1 = (c0 + 1) >> 2, qA1 = ((c0 + 1) & 3) * 8;

    const __half* gA = g_y + (size_t)row0 * CC;
    const __half* gB = g_w + (size_t)col0 * CC;

    auto load_stage = [&](int st, int k0) {
        __half* Af = sm + st * PSTG;
        __half* Bf = Af + PPL;
        cp16(Af + rA0 * PST + qA0, gA + (size_t)rA0 * CC + k0 + qA0);
        cp16(Af + rA1 * PST + qA1, gA + (size_t)rA1 * CC + k0 + qA1);
        cp16(Bf + rA0 * PST + qA0, gB + (size_t)rA0 * CC + k0 + qA0);
        cp16(Bf + rA1 * PST + qA1, gB + (size_t)rA1 * CC + k0 + qA1);
        CP_COMMIT();
    };

    float c[2][8][4];
#pragma unroll
    for (int mf = 0; mf < 2; mf++)
#pragma unroll
        for (int nf = 0; nf < 8; nf++)
#pragma unroll
            for (int r = 0; r < 4; r++) c[mf][nf][r] = 0.0f;

    load_stage(0, 0);

    for (int kt = 0; kt < 8; kt++) {
        if (kt + 1 < 8) {
            load_stage((kt + 1) & 1, (kt + 1) * 32);
            CP_WAIT(1);
        } else {
            CP_WAIT(0);
        }
        __syncthreads();

        __half* Af = sm + (kt & 1) * PSTG;
        __half* Bf = Af + PPL;

#pragma unroll
        for (int kk = 0; kk < 32; kk += 16) {
            uint32_t bh[8][2];
#pragma unroll
            for (int np = 0; np < 4; np++) {
                uint32_t t4[4];
                int brow = n_off + np * 16 + ((lane >> 4) << 3) + (lane & 7);
                int bcol = kk + ((lane >> 3) & 1) * 8;
                ldm_x4(t4, smem_u32(Bf + brow * PST + bcol));
                bh[2 * np][0] = t4[0]; bh[2 * np][1] = t4[1];
                bh[2 * np + 1][0] = t4[2]; bh[2 * np + 1][1] = t4[3];
            }
#pragma unroll
            for (int mf = 0; mf < 2; mf++) {
                uint32_t af[4];
                int arow = m_off + mf * 16 + l16;
                ldm_x4(af, smem_u32(Af + arow * PST + kk + (lane >> 4) * 8));
#pragma unroll
                for (int nf = 0; nf < 8; nf++)
                    mma_f16(c[mf][nf], af, bh[nf][0], bh[nf][1]);
            }
        }
        __syncthreads();
    }

#pragma unroll
    for (int mf = 0; mf < 2; mf++) {
#pragma unroll
        for (int nf = 0; nf < 8; nf++) {
            int rg = row0 + m_off + mf * 16 + (lane >> 2);
            int cg = col0 + n_off + nf * 8 + (lane & 3) * 2;
            float b0 = bias[cg], b1 = bias[cg + 1];
            float2* o0 = (float2*)(out + (size_t)rg * CC + cg);
            float2* o1 = (float2*)(out + (size_t)(rg + 8) * CC + cg);
            *o0 = make_float2(c[mf][nf][0] + b0, c[mf][nf][1] + b1);
            *o1 = make_float2(c[mf][nf][2] + b0, c[mf][nf][3] + b1);
        }
    }
}

// ---------------- launch ----------------
extern "C" void kernel_launch(void* const* d_in, const int* in_sizes, int n_in,
                              void* d_out, int out_size) {
    const float* qkv         = (const float*)d_in[0];
    const float* sim         = (const float*)d_in[1];
    const float* proj_w      = (const float*)d_in[2];
    const float* proj_b      = (const float*)d_in[3];
    const float* logit_scale = (const float*)d_in[4];
    float* out = (float*)d_out;

    k_argmax_hist<<<BB * NCH, CHSZ>>>(sim, proj_w);
    k_scan<<<BB, 256>>>();
    k_scatter_par<<<BB * NCH, CHSZ>>>();

    // h fastest: 8 sibling head-blocks of one (b,g) co-run and share token rows in L2
    cudaFuncSetAttribute(k_attn_mma, cudaFuncAttributeMaxDynamicSharedMemorySize, SMEM_ATT_BYTES);
    k_attn_mma<<<dim3(HH, NG, BB), 128, SMEM_ATT_BYTES>>>(qkv, logit_scale);

    cudaFuncSetAttribute(k_proj2, cudaFuncAttributeMaxDynamicSharedMemorySize, SMEM_PROJ_BYTES);
    k_proj2<<<dim3((BB * NN) / 128, CC / 128), 256, SMEM_PROJ_BYTES>>>(proj_b, out);
}

// round 13
// speedup vs baseline: 1.5966x; 1.1203x over previous
#include <cuda_runtime.h>
#include <cuda_bf16.h>
#include <cuda_fp16.h>
#include <math.h>
#include <stdint.h>

// Problem constants (fixed by the benchmark shapes)
#define BB   4
#define NN   16384
#define CC   256
#define C3   768
#define TT   64
#define HH   8
#define DD   32
#define GS   128
#define NG   128
#define NCH  128
#define CHSZ 128

// -------- scratch (device globals) --------
__device__ int   g_tkid[BB * NN];
__device__ int   g_sortidx[BB * NN];
__device__ int   g_hist[BB * TT * NCH];
__device__ __half g_y[(size_t)BB * NN * CC];     // attention out, single fp16 plane
__device__ __half g_w[CC * CC];                  // W fp16 (1-term)

// ---------------- PTX helpers ----------------
__device__ __forceinline__ uint32_t smem_u32(const void* p) {
    return (uint32_t)__cvta_generic_to_shared(p);
}
__device__ __forceinline__ void ldm_x4(uint32_t* r, uint32_t a) {
    asm volatile("ldmatrix.sync.aligned.m8n8.x4.shared.b16 {%0,%1,%2,%3},[%4];"
                 : "=r"(r[0]), "=r"(r[1]), "=r"(r[2]), "=r"(r[3]) : "r"(a));
}
__device__ __forceinline__ void ldm_x4_t(uint32_t* r, uint32_t a) {
    asm volatile("ldmatrix.sync.aligned.m8n8.x4.trans.shared.b16 {%0,%1,%2,%3},[%4];"
                 : "=r"(r[0]), "=r"(r[1]), "=r"(r[2]), "=r"(r[3]) : "r"(a));
}
__device__ __forceinline__ void mma_bf16(float* c, const uint32_t* a, uint32_t b0, uint32_t b1) {
    asm volatile(
        "mma.sync.aligned.m16n8k16.row.col.f32.bf16.bf16.f32 "
        "{%0,%1,%2,%3},{%4,%5,%6,%7},{%8,%9},{%0,%1,%2,%3};"
        : "+f"(c[0]), "+f"(c[1]), "+f"(c[2]), "+f"(c[3])
        : "r"(a[0]), "r"(a[1]), "r"(a[2]), "r"(a[3]), "r"(b0), "r"(b1));
}
__device__ __forceinline__ void mma_f16(float* c, const uint32_t* a, uint32_t b0, uint32_t b1) {
    asm volatile(
        "mma.sync.aligned.m16n8k16.row.col.f32.f16.f16.f32 "
        "{%0,%1,%2,%3},{%4,%5,%6,%7},{%8,%9},{%0,%1,%2,%3};"
        : "+f"(c[0]), "+f"(c[1]), "+f"(c[2]), "+f"(c[3])
        : "r"(a[0]), "r"(a[1]), "r"(a[2]), "r"(a[3]), "r"(b0), "r"(b1));
}
__device__ __forceinline__ uint32_t packh2(float x, float y) {
    __half2 t = __floats2half2_rn(x, y);
    return *(uint32_t*)&t;
}
__device__ __forceinline__ void cp16(void* smem_dst, const void* gsrc) {
    asm volatile("cp.async.cg.shared.global [%0], [%1], 16;"
                 :: "r"(smem_u32(smem_dst)), "l"(gsrc));
}
#define CP_COMMIT()  asm volatile("cp.async.commit_group;")
#define CP_WAIT(N)   asm volatile("cp.async.wait_group %0;" :: "n"(N))

extern __shared__ __align__(16) char dynsm[];

// ---------------- 1+2a) fused argmax + histogram + W fp16 convert ----------------
__global__ void k_argmax_hist(const float* __restrict__ sim, const float* __restrict__ W) {
    __shared__ int h[TT];
    int b  = blockIdx.x / NCH;
    int ch = blockIdx.x % NCH;
    int t  = threadIdx.x;
    {
        int wi = blockIdx.x * CHSZ + t;
        g_w[wi] = __float2half_rn(W[wi]);
    }
    if (t < TT) h[t] = 0;
    int idx = b * NN + ch * CHSZ + t;
    const float4* p = (const float4*)(sim + (size_t)idx * TT);
    float best = -3.402823466e38f;
    int bi = 0;
#pragma unroll
    for (int i = 0; i < 16; i++) {
        float4 v = p[i];
        if (v.x > best) { best = v.x; bi = 4 * i + 0; }
        if (v.y > best) { best = v.y; bi = 4 * i + 1; }
        if (v.z > best) { best = v.z; bi = 4 * i + 2; }
        if (v.w > best) { best = v.w; bi = 4 * i + 3; }
    }
    g_tkid[idx] = bi;
    __syncthreads();
    atomicAdd(&h[bi], 1);
    __syncthreads();
    if (t < TT)
        g_hist[(b * TT + t) * NCH + ch] = h[t];
}

// ---------------- 2b) exclusive scan ----------------
__global__ void k_scan() {
    __shared__ int tot[256];
    int b = blockIdx.x;
    int* base = g_hist + b * TT * NCH;
    int t = threadIdx.x;
    int v[32];
    int s = 0;
#pragma unroll
    for (int i = 0; i < 32; i++) { v[i] = base[t * 32 + i]; s += v[i]; }
    tot[t] = s;
    __syncthreads();
    if (t == 0) {
        int acc = 0;
        for (int i = 0; i < 256; i++) { int x = tot[i]; tot[i] = acc; acc += x; }
    }
    __syncthreads();
    int ex = tot[t];
#pragma unroll
    for (int i = 0; i < 32; i++) { int x = v[i]; base[t * 32 + i] = ex; ex += x; }
}

// ---------------- 2c) parallel stable scatter ----------------
__global__ void k_scatter_par() {
    __shared__ int whist[4][TT];
    int b  = blockIdx.x / NCH;
    int ch = blockIdx.x % NCH;
    int t  = threadIdx.x;
    int lane = t & 31, w = t >> 5;
    ((int*)whist)[t] = 0;
    ((int*)whist)[t + 128] = 0;
    int key = g_tkid[b * NN + ch * CHSZ + t];
    __syncthreads();
    unsigned mask = __match_any_sync(0xffffffffu, key);
    int wrank = __popc(mask & ((1u << lane) - 1u));
    if (lane == (__ffs(mask) - 1))
        whist[w][key] = __popc(mask);
    __syncthreads();
    int off = 0;
#pragma unroll
    for (int w2 = 0; w2 < 3; w2++)
        if (w2 < w) off += whist[w2][key];
    int pos = g_hist[(b * TT + key) * NCH + ch] + off + wrank;
    g_sortidx[b * NN + pos] = ch * CHSZ + t;
}

// ---------------- 3) tensor-core attention, flash-chunked (R11 config) ----------------
// Grid = (HH, NG, BB): h fastest so sibling head-blocks co-run and tile each
// token's contiguous 3KB row across L2.
// 256 threads = 8 warps, warp owns 16 query rows. Flash chunks of 64 cols.
// Gather: wavefront-minimal (8 lanes per 128B token-slice).
// QK: bf16x3. PV: fp16. Output y: single fp16 plane.
#define AST 40
#define SM_Q_HI 0
#define SM_Q_LO (128 * AST)
#define SM_K_HI (2 * 128 * AST)
#define SM_K_LO (3 * 128 * AST)
#define SM_VF   (4 * 128 * AST)
#define SM_TOK  (5 * 128 * AST)
#define SMEM_ATT_BYTES (5 * 128 * AST * 2 + 128 * 4)

__global__ void __launch_bounds__(256, 3)
k_attn_mma(const float* __restrict__ qkv, const float* __restrict__ logit_scale) {
    __nv_bfloat16* sm = (__nv_bfloat16*)dynsm;
    __nv_bfloat16* Qh = sm + SM_Q_HI;
    __nv_bfloat16* Ql = sm + SM_Q_LO;
    __nv_bfloat16* Kh = sm + SM_K_HI;
    __nv_bfloat16* Kl = sm + SM_K_LO;
    __half*        Vf = (__half*)(sm + SM_VF);
    int* toks = (int*)(sm + SM_TOK);

    int h = blockIdx.x, g = blockIdx.y, b = blockIdx.z;
    int tid = threadIdx.x, lane = tid & 31, warp = tid >> 5;

    // ---- stage sorted token ids ----
    if (tid < GS) toks[tid] = g_sortidx[b * NN + g * GS + tid];
    __syncthreads();

    // ---- wavefront-minimal gather ----
    // lane group: row = i2*32 + (tid>>3), sub = tid&7 (16B unit within 128B slice).
    // 8 consecutive lanes cover one full 128B line per LDG.
    {
        const float* qb = qkv + (size_t)b * NN * C3 + h * DD;
        int rsub  = tid & 7;
        int rbase = tid >> 3;                       // 0..31
#pragma unroll
        for (int tsel = 0; tsel < 3; tsel++) {
            int rw[4];
            const float4* ap[4];
#pragma unroll
            for (int i2 = 0; i2 < 4; i2++) {
                rw[i2] = i2 * 32 + rbase;
                ap[i2] = (const float4*)(qb + (size_t)toks[rw[i2]] * C3 + tsel * CC + rsub * 4);
            }
#pragma unroll
            for (int i2 = 0; i2 < 4; i2++) {
                float4 x = *ap[i2];
                int row = rw[i2];
                if (tsel < 2) {
                    __nv_bfloat162 h01 = __floats2bfloat162_rn(x.x, x.y);
                    __nv_bfloat162 h23 = __floats2bfloat162_rn(x.z, x.w);
                    float2 f01 = __bfloat1622float2(h01);
                    float2 f23 = __bfloat1622float2(h23);
                    __nv_bfloat162 l01 = __floats2bfloat162_rn(x.x - f01.x, x.y - f01.y);
                    __nv_bfloat162 l23 = __floats2bfloat162_rn(x.z - f23.x, x.w - f23.y);
                    __nv_bfloat16* dh = (tsel == 0 ? Qh : Kh) + row * AST + rsub * 4;
                    __nv_bfloat16* dl = (tsel == 0 ? Ql : Kl) + row * AST + rsub * 4;
                    *(uint2*)dh = make_uint2(*(uint32_t*)&h01, *(uint32_t*)&h23);
                    *(uint2*)dl = make_uint2(*(uint32_t*)&l01, *(uint32_t*)&l23);
                } else {
                    __half2 p01 = __floats2half2_rn(x.x, x.y);
                    __half2 p23 = __floats2half2_rn(x.z, x.w);
                    *(uint2*)(Vf + row * AST + rsub * 4) =
                        make_uint2(*(uint32_t*)&p01, *(uint32_t*)&p23);
                }
            }
        }
    }
    // fold softmax scale and log2(e): p = exp2(s*sc2 - M2)
    float sc2 = __expf(fminf(logit_scale[0], 4.605170185988091f)) * 1.44269504088896f;
    __syncthreads();

    int m0 = warp * 16;
    int l16 = lane & 15;

    uint32_t qh[2][4];
#pragma unroll
    for (int ks = 0; ks < 2; ks++)
        ldm_x4(qh[ks], smem_u32(Qh + (m0 + l16) * AST + ks * 16 + (lane >> 4) * 8));

    float o[4][4];
#pragma unroll
    for (int nf = 0; nf < 4; nf++)
#pragma unroll
        for (int r = 0; r < 4; r++) o[nf][r] = 0.0f;
    float m01 = -1e30f, m23 = -1e30f, l01 = 0.0f, l23 = 0.0f;

#pragma unroll
    for (int chnk = 0; chnk < 2; chnk++) {
        int c0 = chnk * 64;
        uint32_t ql[2][4];
#pragma unroll
        for (int ks = 0; ks < 2; ks++)
            ldm_x4(ql[ks], smem_u32(Ql + (m0 + l16) * AST + ks * 16 + (lane >> 4) * 8));

        float s[8][4];
#pragma unroll
        for (int nf = 0; nf < 8; nf++)
#pragma unroll
            for (int r = 0; r < 4; r++) s[nf][r] = 0.0f;

#pragma unroll
        for (int p2 = 0; p2 < 4; p2++) {
            int j0 = c0 + p2 * 16;
#pragma unroll
            for (int ks = 0; ks < 2; ks++) {
                uint32_t kb[4], kl4[4];
                int krow = j0 + ((lane >> 4) << 3) + (lane & 7);
                int kcol = ks * 16 + ((lane >> 3) & 1) * 8;
                ldm_x4(kb,  smem_u32(Kh + krow * AST + kcol));
                ldm_x4(kl4, smem_u32(Kl + krow * AST + kcol));
                mma_bf16(s[2 * p2],     qh[ks], kb[0],  kb[1]);
                mma_bf16(s[2 * p2],     qh[ks], kl4[0], kl4[1]);
                mma_bf16(s[2 * p2],     ql[ks], kb[0],  kb[1]);
                mma_bf16(s[2 * p2 + 1], qh[ks], kb[2],  kb[3]);
                mma_bf16(s[2 * p2 + 1], qh[ks], kl4[2], kl4[3]);
                mma_bf16(s[2 * p2 + 1], ql[ks], kb[2],  kb[3]);
            }
        }

        // scale fold + chunk row-max (quad shfl)
        float cm01 = -1e30f, cm23 = -1e30f;
#pragma unroll
        for (int nf = 0; nf < 8; nf++) {
#pragma unroll
            for (int r = 0; r < 4; r++) s[nf][r] *= sc2;
            cm01 = fmaxf(cm01, fmaxf(s[nf][0], s[nf][1]));
            cm23 = fmaxf(cm23, fmaxf(s[nf][2], s[nf][3]));
        }
        cm01 = fmaxf(cm01, __shfl_xor_sync(0xffffffffu, cm01, 1));
        cm01 = fmaxf(cm01, __shfl_xor_sync(0xffffffffu, cm01, 2));
        cm23 = fmaxf(cm23, __shfl_xor_sync(0xffffffffu, cm23, 1));
        cm23 = fmaxf(cm23, __shfl_xor_sync(0xffffffffu, cm23, 2));

        // online update
        float nm01 = fmaxf(m01, cm01), nm23 = fmaxf(m23, cm23);
        float cor01 = exp2f(m01 - nm01), cor23 = exp2f(m23 - nm23);
        m01 = nm01; m23 = nm23;
#pragma unroll
        for (int nf = 0; nf < 4; nf++) {
            o[nf][0] *= cor01; o[nf][1] *= cor01;
            o[nf][2] *= cor23; o[nf][3] *= cor23;
        }

        float sum01 = 0.0f, sum23 = 0.0f;
#pragma unroll
        for (int nf = 0; nf < 8; nf++) {
            float e0 = exp2f(s[nf][0] - m01);
            float e1 = exp2f(s[nf][1] - m01);
            float e2 = exp2f(s[nf][2] - m23);
            float e3 = exp2f(s[nf][3] - m23);
            s[nf][0] = e0; s[nf][1] = e1; s[nf][2] = e2; s[nf][3] = e3;
            sum01 += e0 + e1;
            sum23 += e2 + e3;
        }
        sum01 += __shfl_xor_sync(0xffffffffu, sum01, 1);
        sum01 += __shfl_xor_sync(0xffffffffu, sum01, 2);
        sum23 += __shfl_xor_sync(0xffffffffu, sum23, 1);
        sum23 += __shfl_xor_sync(0xffffffffu, sum23, 2);
        l01 = l01 * cor01 + sum01;
        l23 = l23 * cor23 + sum23;

        // PV over this chunk's 64 k-rows
#pragma unroll
        for (int kj = 0; kj < 4; kj++) {
            int f0 = 2 * kj, f1 = 2 * kj + 1;
            uint32_t ph[4];
            ph[0] = packh2(s[f0][0], s[f0][1]);
            ph[1] = packh2(s[f0][2], s[f0][3]);
            ph[2] = packh2(s[f1][0], s[f1][1]);
            ph[3] = packh2(s[f1][2], s[f1][3]);
            int vrow = c0 + kj * 16 + l16;
#pragma unroll
            for (int dh2 = 0; dh2 < 2; dh2++) {
                uint32_t vf[4];
                ldm_x4_t(vf, smem_u32(Vf + vrow * AST + dh2 * 16 + ((lane >> 4) << 3)));
                mma_f16(o[2 * dh2],     ph, vf[0], vf[1]);
                mma_f16(o[2 * dh2 + 1], ph, vf[2], vf[3]);
            }
        }
    }

    // ---- epilogue: normalize, fp16, scatter to original token rows ----
    float inv0 = 1.0f / l01, inv1 = 1.0f / l23;
    int r0 = m0 + (lane >> 2);
    int tok0 = toks[r0], tok1 = toks[r0 + 8];
    size_t ob0 = (size_t)(b * NN + tok0) * CC + h * DD + (lane & 3) * 2;
    size_t ob1 = (size_t)(b * NN + tok1) * CC + h * DD + (lane & 3) * 2;
#pragma unroll
    for (int nf = 0; nf < 4; nf++) {
        *(__half2*)(g_y + ob0 + nf * 8) = __floats2half2_rn(o[nf][0] * inv0, o[nf][1] * inv0);
        *(__half2*)(g_y + ob1 + nf * 8) = __floats2half2_rn(o[nf][2] * inv1, o[nf][3] * inv1);
    }
}

// ---------------- 4) projection: fp16 1-term MMA, cp.async double-buffered ----------------
// out = y(fp16) @ W(fp16)^T + bias. 2 planes per stage: Af, Bf.
#define PST  40
#define PPL  (128 * PST)
#define PSTG (2 * PPL)
#define SMEM_PROJ_BYTES (2 * PSTG * 2)

__global__ void __launch_bounds__(256)
k_proj2(const float* __restrict__ bias, float* __restrict__ out) {
    __half* sm = (__half*)dynsm;

    int tid  = threadIdx.x;
    int lane = tid & 31;
    int warp = tid >> 5;
    int row0 = blockIdx.x * 128;
    int col0 = blockIdx.y * 128;
    int m_off = (warp & 3) * 32;
    int n_off = (warp >> 2) * 64;
    int l16 = lane & 15;

    int c0 = tid * 2;
    int rA0 = c0 >> 2, qA0 = (c0 & 3) * 8;
    int rA1 = (c0 + 1) >> 2, qA1 = ((c0 + 1) & 3) * 8;

    const __half* gA = g_y + (size_t)row0 * CC;
    const __half* gB = g_w + (size_t)col0 * CC;

    auto load_stage = [&](int st, int k0) {
        __half* Af = sm + st * PSTG;
        __half* Bf = Af + PPL;
        cp16(Af + rA0 * PST + qA0, gA + (size_t)rA0 * CC + k0 + qA0);
        cp16(Af + rA1 * PST + qA1, gA + (size_t)rA1 * CC + k0 + qA1);
        cp16(Bf + rA0 * PST + qA0, gB + (size_t)rA0 * CC + k0 + qA0);
        cp16(Bf + rA1 * PST + qA1, gB + (size_t)rA1 * CC + k0 + qA1);
        CP_COMMIT();
    };

    float c[2][8][4];
#pragma unroll
    for (int mf = 0; mf < 2; mf++)
#pragma unroll
        for (int nf = 0; nf < 8; nf++)
#pragma unroll
            for (int r = 0; r < 4; r++) c[mf][nf][r] = 0.0f;

    load_stage(0, 0);

    for (int kt = 0; kt < 8; kt++) {
        if (kt + 1 < 8) {
            load_stage((kt + 1) & 1, (kt + 1) * 32);
            CP_WAIT(1);
        } else {
            CP_WAIT(0);
        }
        __syncthreads();

        __half* Af = sm + (kt & 1) * PSTG;
        __half* Bf = Af + PPL;

#pragma unroll
        for (int kk = 0; kk < 32; kk += 16) {
            uint32_t bh[8][2];
#pragma unroll
            for (int np = 0; np < 4; np++) {
                uint32_t t4[4];
                int brow = n_off + np * 16 + ((lane >> 4) << 3) + (lane & 7);
                int bcol = kk + ((lane >> 3) & 1) * 8;
                ldm_x4(t4, smem_u32(Bf + brow * PST + bcol));
                bh[2 * np][0] = t4[0]; bh[2 * np][1] = t4[1];
                bh[2 * np + 1][0] = t4[2]; bh[2 * np + 1][1] = t4[3];
            }
#pragma unroll
            for (int mf = 0; mf < 2; mf++) {
                uint32_t af[4];
                int arow = m_off + mf * 16 + l16;
                ldm_x4(af, smem_u32(Af + arow * PST + kk + (lane >> 4) * 8));
#pragma unroll
                for (int nf = 0; nf < 8; nf++)
                    mma_f16(c[mf][nf], af, bh[nf][0], bh[nf][1]);
            }
        }
        __syncthreads();
    }

#pragma unroll
    for (int mf = 0; mf < 2; mf++) {
#pragma unroll
        for (int nf = 0; nf < 8; nf++) {
            int rg = row0 + m_off + mf * 16 + (lane >> 2);
            int cg = col0 + n_off + nf * 8 + (lane & 3) * 2;
            float b0 = bias[cg], b1 = bias[cg + 1];
            float2* o0 = (float2*)(out + (size_t)rg * CC + cg);
            float2* o1 = (float2*)(out + (size_t)(rg + 8) * CC + cg);
            *o0 = make_float2(c[mf][nf][0] + b0, c[mf][nf][1] + b1);
            *o1 = make_float2(c[mf][nf][2] + b0, c[mf][nf][3] + b1);
        }
    }
}

// ---------------- launch ----------------
extern "C" void kernel_launch(void* const* d_in, const int* in_sizes, int n_in,
                              void* d_out, int out_size) {
    const float* qkv         = (const float*)d_in[0];
    const float* sim         = (const float*)d_in[1];
    const float* proj_w      = (const float*)d_in[2];
    const float* proj_b      = (const float*)d_in[3];
    const float* logit_scale = (const float*)d_in[4];
    float* out = (float*)d_out;

    k_argmax_hist<<<BB * NCH, CHSZ>>>(sim, proj_w);
    k_scan<<<BB, 256>>>();
    k_scatter_par<<<BB * NCH, CHSZ>>>();

    // h fastest: 8 sibling head-blocks of one (b,g) co-run and share token rows in L2
    cudaFuncSetAttribute(k_attn_mma, cudaFuncAttributeMaxDynamicSharedMemorySize, SMEM_ATT_BYTES);
    k_attn_mma<<<dim3(HH, NG, BB), 256, SMEM_ATT_BYTES>>>(qkv, logit_scale);

    cudaFuncSetAttribute(k_proj2, cudaFuncAttributeMaxDynamicSharedMemorySize, SMEM_PROJ_BYTES);
    k_proj2<<<dim3((BB * NN) / 128, CC / 128), 256, SMEM_PROJ_BYTES>>>(proj_b, out);
}